// round 4
// baseline (speedup 1.0000x reference)
#include <cuda_runtime.h>

#define BB 4
#define SS 2048
#define DD 1024
#define HH 16
#define HD 64
#define MM (BB*SS)   // 8192 rows

// ---------------- scratch (no allocations allowed) ----------------
__device__ float g_qh [(size_t)BB*HH*SS*HD];   // [B,H,S,HD]
__device__ float g_kh [(size_t)BB*HH*SS*HD];
__device__ float g_vh [(size_t)BB*HH*SS*HD];
__device__ float g_sfx[(size_t)BB*HH*SS*HD];   // suffix sums of V per head
__device__ float g_ctx[(size_t)MM*DD];         // attention output, [B,S,D]
__device__ float g_ctot[(size_t)BB*HH*32*HD];  // per-chunk totals
__device__ float g_csfx[(size_t)BB*HH*32*HD];  // suffix of chunk totals

// ---------------- GEMM: out = A[M,K] @ W[K,N] + bias (+res) ----------------
// MODE 0: write to head layout [B,H,S,HD]; MODE 1: plain [M,N] + residual
template<int MODE>
__global__ __launch_bounds__(256)
void gemm_k(const float* __restrict__ A, const float* __restrict__ W,
            const float* __restrict__ bias, const float* __restrict__ res,
            float* __restrict__ out)
{
    __shared__ float As[16][72];   // transposed A tile, padded (72%32=8 -> conflict-free)
    __shared__ float Bs[16][72];
    const int tid = threadIdx.x;
    const int ty = tid >> 4, tx = tid & 15;
    const int m0 = blockIdx.y * 64, n0 = blockIdx.x * 64;
    const int arow = tid >> 2, aq = tid & 3;
    const int brow = tid >> 4, bc = tid & 15;
    const float* Ap = A + (size_t)(m0 + arow) * DD + aq * 4;
    const float* Wp = W + (size_t)brow * DD + n0 + bc * 4;

    float acc[4][4];
    #pragma unroll
    for (int i = 0; i < 4; i++)
        #pragma unroll
        for (int j = 0; j < 4; j++) acc[i][j] = 0.f;

    for (int k0 = 0; k0 < DD; k0 += 16) {
        float4 av = *(const float4*)(Ap + k0);
        float4 wv = *(const float4*)(Wp + (size_t)k0 * DD);
        As[aq*4+0][arow] = av.x;
        As[aq*4+1][arow] = av.y;
        As[aq*4+2][arow] = av.z;
        As[aq*4+3][arow] = av.w;
        *(float4*)&Bs[brow][bc*4] = wv;
        __syncthreads();
        #pragma unroll
        for (int kk = 0; kk < 16; kk++) {
            float4 a = *(const float4*)&As[kk][ty*4];
            float4 b = *(const float4*)&Bs[kk][tx*4];
            acc[0][0] += a.x*b.x; acc[0][1] += a.x*b.y; acc[0][2] += a.x*b.z; acc[0][3] += a.x*b.w;
            acc[1][0] += a.y*b.x; acc[1][1] += a.y*b.y; acc[1][2] += a.y*b.z; acc[1][3] += a.y*b.w;
            acc[2][0] += a.z*b.x; acc[2][1] += a.z*b.y; acc[2][2] += a.z*b.z; acc[2][3] += a.z*b.w;
            acc[3][0] += a.w*b.x; acc[3][1] += a.w*b.y; acc[3][2] += a.w*b.z; acc[3][3] += a.w*b.w;
        }
        __syncthreads();
    }

    const int nb = n0 + tx*4;
    float4 bv4 = *(const float4*)(bias + nb);
    #pragma unroll
    for (int i = 0; i < 4; i++) {
        const int m = m0 + ty*4 + i;
        float4 o;
        o.x = acc[i][0] + bv4.x; o.y = acc[i][1] + bv4.y;
        o.z = acc[i][2] + bv4.z; o.w = acc[i][3] + bv4.w;
        if (MODE == 0) {
            const int b = m >> 11, s = m & (SS - 1);
            const int h = n0 >> 6;                 // BN=64 == HD -> one head per tile col
            *(float4*)(out + (((size_t)(b*HH + h))*SS + s)*HD + tx*4) = o;
        } else {
            const size_t idx = (size_t)m*DD + nb;
            float4 r = *(const float4*)(res + idx);
            o.x += r.x; o.y += r.y; o.z += r.z; o.w += r.w;
            *(float4*)(out + idx) = o;
        }
    }
}

// ---------------- suffix sums of V per (b,h): sfx[q] = sum_{k>q} v[k] ----------------
__global__ void sfxA_k(const float* __restrict__ vh, float* __restrict__ sfx,
                       float* __restrict__ ctot)
{
    const int bh = blockIdx.y, c = blockIdx.x, d = threadIdx.x;
    const size_t base = (size_t)bh*SS*HD + d;
    float acc = 0.f;
    for (int s = c*64 + 63; s >= c*64; s--) {
        sfx[base + (size_t)s*HD] = acc;
        acc += vh[base + (size_t)s*HD];
    }
    ctot[((size_t)bh*32 + c)*HD + d] = acc;
}

__global__ void sfxB_k(const float* __restrict__ ctot, float* __restrict__ csfx)
{
    const int bh = blockIdx.x, d = threadIdx.x;
    float acc = 0.f;
    for (int c = 31; c >= 0; c--) {
        csfx[((size_t)bh*32 + c)*HD + d] = acc;
        acc += ctot[((size_t)bh*32 + c)*HD + d];
    }
}

__global__ void sfxC_k(const float* __restrict__ csfx, float* __restrict__ sfx)
{
    const int bh = blockIdx.y, c = blockIdx.x, d = threadIdx.x;
    const float add = csfx[((size_t)bh*32 + c)*HD + d];
    const size_t base = (size_t)bh*SS*HD + d;
    for (int s = c*64; s < c*64 + 64; s++)
        sfx[base + (size_t)s*HD] += add;
}

// ---------------- attention: online softmax over causal keys, masked part folded in ----------------
__global__ __launch_bounds__(64)
void attn_k(const float* __restrict__ qh, const float* __restrict__ kh,
            const float* __restrict__ vh, const float* __restrict__ sfx,
            float* __restrict__ ctx)
{
    __shared__ float Ks[32][64];
    __shared__ float Vs[32][64];
    const int bh = blockIdx.y;
    const int q = blockIdx.x*64 + threadIdx.x;

    const float* qp = qh + ((size_t)bh*SS + q)*HD;
    float qr[64];
    #pragma unroll
    for (int i = 0; i < 16; i++) {
        float4 t = ((const float4*)qp)[i];
        qr[4*i+0] = t.x * 0.125f; qr[4*i+1] = t.y * 0.125f;   // fold 1/sqrt(HD)
        qr[4*i+2] = t.z * 0.125f; qr[4*i+3] = t.w * 0.125f;
    }
    float O[64];
    const float* sp = sfx + ((size_t)bh*SS + q)*HD;
    #pragma unroll
    for (int i = 0; i < 16; i++) {
        float4 t = ((const float4*)sp)[i];
        O[4*i+0] = t.x; O[4*i+1] = t.y; O[4*i+2] = t.z; O[4*i+3] = t.w;
    }
    float mv = 0.f;                      // masked entries contribute score 0
    float l  = (float)(SS - 1 - q);      // count of masked entries, each exp(0-0)=1

    const int qmax = blockIdx.x*64 + 63;
    const int ntiles = qmax/32 + 1;
    for (int kt = 0; kt < ntiles; kt++) {
        const int kbase = kt*32;
        const float* Kg = kh + ((size_t)bh*SS + kbase)*HD;
        const float* Vg = vh + ((size_t)bh*SS + kbase)*HD;
        #pragma unroll
        for (int j = 0; j < 8; j++) {
            int g = j*64 + threadIdx.x;     // 0..511 float4 granules
            int r = g >> 4, c = g & 15;
            ((float4*)Ks[r])[c] = ((const float4*)Kg)[g];
            ((float4*)Vs[r])[c] = ((const float4*)Vg)[g];
        }
        __syncthreads();
        int kend = q - kbase + 1;
        if (kend > 32) kend = 32;
        for (int kk = 0; kk < kend; kk++) {
            const float4* Kr = (const float4*)Ks[kk];
            float s0 = 0.f, s1 = 0.f, s2 = 0.f, s3 = 0.f;
            #pragma unroll
            for (int i = 0; i < 16; i++) {
                float4 kv = Kr[i];
                s0 += qr[4*i+0]*kv.x; s1 += qr[4*i+1]*kv.y;
                s2 += qr[4*i+2]*kv.z; s3 += qr[4*i+3]*kv.w;
            }
            float s = (s0 + s1) + (s2 + s3);
            if (s > mv) {                                  // rare (~ln(S) times total)
                float cf = __expf(mv - s);
                l *= cf;
                #pragma unroll
                for (int d = 0; d < 64; d++) O[d] *= cf;
                mv = s;
            }
            float p = __expf(s - mv);
            l += p;
            const float4* Vr = (const float4*)Vs[kk];
            #pragma unroll
            for (int i = 0; i < 16; i++) {
                float4 vv = Vr[i];
                O[4*i+0] += p*vv.x; O[4*i+1] += p*vv.y;
                O[4*i+2] += p*vv.z; O[4*i+3] += p*vv.w;
            }
        }
        __syncthreads();
    }

    const float inv = 1.f / l;
    const int b = bh / HH, h = bh % HH;
    float* op = ctx + ((size_t)(b*SS + q))*DD + h*HD;
    #pragma unroll
    for (int i = 0; i < 16; i++) {
        float4 t;
        t.x = O[4*i+0]*inv; t.y = O[4*i+1]*inv;
        t.z = O[4*i+2]*inv; t.w = O[4*i+3]*inv;
        ((float4*)op)[i] = t;
    }
}

// ---------------- LayerNorm (in place on d_out) ----------------
__global__ __launch_bounds__(256)
void ln_k(float* __restrict__ out, const float* __restrict__ gamma,
          const float* __restrict__ beta)
{
    const int row = blockIdx.x;
    float* p = out + (size_t)row*DD;
    const int t = threadIdx.x;
    float4 v = ((const float4*)p)[t];
    float sum = v.x + v.y + v.z + v.w;
    float sq  = v.x*v.x + v.y*v.y + v.z*v.z + v.w*v.w;
    #pragma unroll
    for (int o = 16; o > 0; o >>= 1) {
        sum += __shfl_xor_sync(0xffffffffu, sum, o);
        sq  += __shfl_xor_sync(0xffffffffu, sq,  o);
    }
    __shared__ float s1[8], s2[8];
    if ((t & 31) == 0) { s1[t >> 5] = sum; s2[t >> 5] = sq; }
    __syncthreads();
    __shared__ float smu, srstd;
    if (t < 32) {
        float a = (t < 8) ? s1[t] : 0.f;
        float b = (t < 8) ? s2[t] : 0.f;
        #pragma unroll
        for (int o = 4; o > 0; o >>= 1) {
            a += __shfl_xor_sync(0xffffffffu, a, o);
            b += __shfl_xor_sync(0xffffffffu, b, o);
        }
        if (t == 0) {
            float mu  = a * (1.f/DD);
            float var = b * (1.f/DD) - mu*mu;
            smu = mu;
            srstd = rsqrtf(var + 1e-5f);
        }
    }
    __syncthreads();
    const float mu = smu, rs = srstd;
    float4 g  = ((const float4*)gamma)[t];
    float4 be = ((const float4*)beta)[t];
    v.x = (v.x - mu)*rs*g.x + be.x;
    v.y = (v.y - mu)*rs*g.y + be.y;
    v.z = (v.z - mu)*rs*g.z + be.z;
    v.w = (v.w - mu)*rs*g.w + be.w;
    ((float4*)p)[t] = v;
}

// ---------------- launch ----------------
extern "C" void kernel_launch(void* const* d_in, const int* in_sizes, int n_in,
                              void* d_out, int out_size)
{
    const float* q     = (const float*)d_in[0];
    const float* k     = (const float*)d_in[1];
    const float* v     = (const float*)d_in[2];
    const float* Wq    = (const float*)d_in[3];
    const float* bq    = (const float*)d_in[4];
    const float* Wk    = (const float*)d_in[5];
    const float* bk    = (const float*)d_in[6];
    const float* Wv    = (const float*)d_in[7];
    const float* bv    = (const float*)d_in[8];
    const float* Wp    = (const float*)d_in[9];
    const float* bp    = (const float*)d_in[10];
    const float* gamma = (const float*)d_in[11];
    const float* beta  = (const float*)d_in[12];
    float* out = (float*)d_out;

    float *qh, *kh, *vh, *sfx, *ctx, *ctot, *csfx;
    cudaGetSymbolAddress((void**)&qh,  g_qh);
    cudaGetSymbolAddress((void**)&kh,  g_kh);
    cudaGetSymbolAddress((void**)&vh,  g_vh);
    cudaGetSymbolAddress((void**)&sfx, g_sfx);
    cudaGetSymbolAddress((void**)&ctx, g_ctx);
    cudaGetSymbolAddress((void**)&ctot, g_ctot);
    cudaGetSymbolAddress((void**)&csfx, g_csfx);

    dim3 gg(DD/64, MM/64);     // (16, 128)
    gemm_k<0><<<gg, 256>>>(q, Wq, bq, nullptr, qh);
    gemm_k<0><<<gg, 256>>>(k, Wk, bk, nullptr, kh);
    gemm_k<0><<<gg, 256>>>(v, Wv, bv, nullptr, vh);

    dim3 gs(32, BB*HH);        // (32, 64)
    sfxA_k<<<gs, 64>>>(vh, sfx, ctot);
    sfxB_k<<<BB*HH, 64>>>(ctot, csfx);
    sfxC_k<<<gs, 64>>>(csfx, sfx);

    attn_k<<<dim3(SS/64, BB*HH), 64>>>(qh, kh, vh, sfx, ctx);

    gemm_k<1><<<gg, 256>>>(ctx, Wp, bp, q, out);
    ln_k<<<MM, 256>>>(out, gamma, beta);
}

// round 7
// speedup vs baseline: 1.5274x; 1.5274x over previous
#include <cuda_runtime.h>
#include <cuda_bf16.h>
#include <cstdint>

#define BB 4
#define SS 2048
#define DD 1024
#define HH 16
#define HD 64
#define MM (BB*SS)   // 8192 rows
#define WSZ (1024*1024)

// ---------------- scratch (no allocations allowed) ----------------
__device__ float g_qh [(size_t)BB*HH*SS*HD];   // [B,H,S,HD]
__device__ float g_kh [(size_t)BB*HH*SS*HD];
__device__ float g_vh [(size_t)BB*HH*SS*HD];
__device__ float g_sfx[(size_t)BB*HH*SS*HD];   // suffix sums of V per head
__device__ float g_ctx[(size_t)MM*DD];         // attention output, [B,S,D]
__device__ float g_ctot[(size_t)BB*HH*32*HD];  // per-chunk totals
__device__ float g_csfx[(size_t)BB*HH*32*HD];  // suffix of chunk totals
__device__ __nv_bfloat16 g_wth[(size_t)4*WSZ]; // W^T hi, [N,K] per weight
__device__ __nv_bfloat16 g_wtl[(size_t)4*WSZ]; // W^T lo
__device__ __nv_bfloat16 g_ah [(size_t)MM*DD]; // activation hi (reused)
__device__ __nv_bfloat16 g_al [(size_t)MM*DD]; // activation lo

// ---------------- helpers ----------------
__device__ __forceinline__ uint32_t smem_u32(const void* p) {
    uint32_t a;
    asm("{ .reg .u64 t; cvta.to.shared.u64 t, %1; cvt.u32.u64 %0, t; }" : "=r"(a) : "l"(p));
    return a;
}
__device__ __forceinline__ void ldsm4(uint32_t* r, uint32_t addr) {
    asm volatile("ldmatrix.sync.aligned.m8n8.x4.shared.b16 {%0,%1,%2,%3}, [%4];"
        : "=r"(r[0]), "=r"(r[1]), "=r"(r[2]), "=r"(r[3]) : "r"(addr));
}
__device__ __forceinline__ void mma16816(float* c, const uint32_t* a, const uint32_t* b) {
    asm volatile("mma.sync.aligned.m16n8k16.row.col.f32.bf16.bf16.f32 "
        "{%0,%1,%2,%3}, {%4,%5,%6,%7}, {%8,%9}, {%0,%1,%2,%3};"
        : "+f"(c[0]), "+f"(c[1]), "+f"(c[2]), "+f"(c[3])
        : "r"(a[0]), "r"(a[1]), "r"(a[2]), "r"(a[3]), "r"(b[0]), "r"(b[1]));
}

// ---------------- fp32 -> bf16 hi/lo split (elementwise, float4) ----------------
__global__ __launch_bounds__(1024)
void convA_k(const float* __restrict__ A, __nv_bfloat16* __restrict__ hi,
             __nv_bfloat16* __restrict__ lo)
{
    size_t i = (size_t)blockIdx.x * blockDim.x + threadIdx.x;   // one float4 each
    float4 v = ((const float4*)A)[i];
    union { __nv_bfloat16 b[4]; uint2 u; } ph, pl;
    #pragma unroll
    for (int j = 0; j < 4; j++) {
        float x = (&v.x)[j];
        __nv_bfloat16 h = __float2bfloat16(x);
        ph.b[j] = h;
        pl.b[j] = __float2bfloat16(x - __bfloat162float(h));
    }
    ((uint2*)hi)[i] = ph.u;
    ((uint2*)lo)[i] = pl.u;
}

// ---------------- W [K,N] fp32 -> W^T [N,K] bf16 hi/lo ----------------
__global__ __launch_bounds__(1024)
void convW_k(const float* __restrict__ W, __nv_bfloat16* __restrict__ hi,
             __nv_bfloat16* __restrict__ lo)
{
    __shared__ float t[32][33];
    const int k0 = blockIdx.y * 32, n0 = blockIdx.x * 32;
    t[threadIdx.y][threadIdx.x] = W[(size_t)(k0 + threadIdx.y) * DD + n0 + threadIdx.x];
    __syncthreads();
    float v = t[threadIdx.x][threadIdx.y];   // = W[k0+tx][n0+ty]
    size_t o = (size_t)(n0 + threadIdx.y) * DD + k0 + threadIdx.x;
    __nv_bfloat16 h = __float2bfloat16(v);
    hi[o] = h;
    lo[o] = __float2bfloat16(v - __bfloat162float(h));
}

// ---------------- mma.sync GEMM: D = Ahi@Bhi + Ahi@Blo + Alo@Bhi (+bias,+res) ------
// A*: [M,K] bf16 row-major. B*: [N,K] bf16 row-major (W transposed).
// CTA 128x128, 8 warps (2m x 4n), warp tile 64x32, K-chunk 32, reg-staged pipeline.
// MODE 0: scatter to head layout [B,H,S,HD]; MODE 1: [M,N] + residual.
template<int MODE>
__global__ __launch_bounds__(256)
void gemm_mma(const __nv_bfloat16* __restrict__ Ah, const __nv_bfloat16* __restrict__ Al,
              const __nv_bfloat16* __restrict__ Bh, const __nv_bfloat16* __restrict__ Bl,
              const float* __restrict__ bias, const float* __restrict__ res,
              float* __restrict__ out)
{
    __shared__ alignas(128) __nv_bfloat16 sAh[128*32];
    __shared__ alignas(128) __nv_bfloat16 sAl[128*32];
    __shared__ alignas(128) __nv_bfloat16 sBh[128*32];
    __shared__ alignas(128) __nv_bfloat16 sBl[128*32];

    const int tid = threadIdx.x, lane = tid & 31, wid = tid >> 5;
    const int wm = (wid & 1) * 64, wn = (wid >> 1) * 32;
    const int m0 = blockIdx.y * 128, n0 = blockIdx.x * 128;

    // ---- staging/store indexing: thread -> (row, two 16B chunks) ----
    const int strow = tid >> 1;
    const int stc0  = (tid & 1) * 2;
    const int stsw  = (strow >> 1) & 3;
    const int ss0   = strow * 4 + (stc0 ^ stsw);
    const int ss1   = strow * 4 + ((stc0 + 1) ^ stsw);
    const __nv_bfloat16* pAh = Ah + (size_t)(m0 + strow) * DD + stc0 * 8;
    const __nv_bfloat16* pAl = Al + (size_t)(m0 + strow) * DD + stc0 * 8;
    const __nv_bfloat16* pBh = Bh + (size_t)(n0 + strow) * DD + stc0 * 8;
    const __nv_bfloat16* pBl = Bl + (size_t)(n0 + strow) * DD + stc0 * 8;
    uint4* s4Ah = (uint4*)sAh; uint4* s4Al = (uint4*)sAl;
    uint4* s4Bh = (uint4*)sBh; uint4* s4Bl = (uint4*)sBl;

    // ---- ldmatrix addressing ----
    const uint32_t aAh = smem_u32(sAh), aAl = smem_u32(sAl);
    const uint32_t aBh = smem_u32(sBh), aBl = smem_u32(sBl);
    const int la15 = lane & 15;
    const uint32_t Aoff = (uint32_t)(wm + la15) * 64;
    const int swA = (la15 >> 1) & 3;
    const uint32_t cA0 = (uint32_t)(((lane >> 4)     ) ^ swA) * 16;
    const uint32_t cA1 = (uint32_t)((2 + (lane >> 4)) ^ swA) * 16;
    const int la7 = lane & 7;
    const uint32_t Boff = (uint32_t)(wn + la7 + ((lane >> 4) << 3)) * 64;
    const int swB = (la7 >> 1) & 3;
    const uint32_t cB0 = (uint32_t)((((lane >> 3) & 1)    ) ^ swB) * 16;
    const uint32_t cB1 = (uint32_t)((2 + ((lane >> 3) & 1)) ^ swB) * 16;

    float acc[4][4][4];
    #pragma unroll
    for (int mi = 0; mi < 4; mi++)
        #pragma unroll
        for (int ni = 0; ni < 4; ni++)
            #pragma unroll
            for (int r = 0; r < 4; r++) acc[mi][ni][r] = 0.f;

    uint4 vah0, vah1, val0, val1, vbh0, vbh1, vbl0, vbl1;
    // prologue: stage chunk 0
    vah0 = *(const uint4*)(pAh);      vah1 = *(const uint4*)(pAh + 8);
    val0 = *(const uint4*)(pAl);      val1 = *(const uint4*)(pAl + 8);
    vbh0 = *(const uint4*)(pBh);      vbh1 = *(const uint4*)(pBh + 8);
    vbl0 = *(const uint4*)(pBl);      vbl1 = *(const uint4*)(pBl + 8);

    for (int kc = 0; kc < 32; kc++) {
        s4Ah[ss0] = vah0; s4Ah[ss1] = vah1;
        s4Al[ss0] = val0; s4Al[ss1] = val1;
        s4Bh[ss0] = vbh0; s4Bh[ss1] = vbh1;
        s4Bl[ss0] = vbl0; s4Bl[ss1] = vbl1;
        __syncthreads();

        if (kc < 31) {   // stage next chunk while computing this one
            const int k0 = (kc + 1) * 32;
            vah0 = *(const uint4*)(pAh + k0);  vah1 = *(const uint4*)(pAh + k0 + 8);
            val0 = *(const uint4*)(pAl + k0);  val1 = *(const uint4*)(pAl + k0 + 8);
            vbh0 = *(const uint4*)(pBh + k0);  vbh1 = *(const uint4*)(pBh + k0 + 8);
            vbl0 = *(const uint4*)(pBl + k0);  vbl1 = *(const uint4*)(pBl + k0 + 8);
        }

        #pragma unroll
        for (int ks = 0; ks < 2; ks++) {
            const uint32_t cA = ks ? cA1 : cA0;
            const uint32_t cB = ks ? cB1 : cB0;
            uint32_t a[4][4], a2[4][4], b[2][4], b2[2][4];
            #pragma unroll
            for (int mi = 0; mi < 4; mi++) ldsm4(a[mi], aAh + Aoff + mi * 1024 + cA);
            #pragma unroll
            for (int nt = 0; nt < 2; nt++) ldsm4(b[nt], aBh + Boff + nt * 1024 + cB);
            #pragma unroll
            for (int mi = 0; mi < 4; mi++)
                #pragma unroll
                for (int ni = 0; ni < 4; ni++)
                    mma16816(acc[mi][ni], a[mi], &b[ni >> 1][(ni & 1) * 2]);   // hi*hi
            #pragma unroll
            for (int nt = 0; nt < 2; nt++) ldsm4(b2[nt], aBl + Boff + nt * 1024 + cB);
            #pragma unroll
            for (int mi = 0; mi < 4; mi++)
                #pragma unroll
                for (int ni = 0; ni < 4; ni++)
                    mma16816(acc[mi][ni], a[mi], &b2[ni >> 1][(ni & 1) * 2]);  // hi*lo
            #pragma unroll
            for (int mi = 0; mi < 4; mi++) ldsm4(a2[mi], aAl + Aoff + mi * 1024 + cA);
            #pragma unroll
            for (int mi = 0; mi < 4; mi++)
                #pragma unroll
                for (int ni = 0; ni < 4; ni++)
                    mma16816(acc[mi][ni], a2[mi], &b[ni >> 1][(ni & 1) * 2]);  // lo*hi
        }
        __syncthreads();
    }

    // ---- epilogue ----
    const int gid = lane >> 2, tig = (lane & 3) * 2;
    #pragma unroll
    for (int mi = 0; mi < 4; mi++) {
        #pragma unroll
        for (int rr = 0; rr < 2; rr++) {
            const int m = m0 + wm + mi * 16 + gid + rr * 8;
            #pragma unroll
            for (int ni = 0; ni < 4; ni++) {
                const int col = n0 + wn + ni * 8 + tig;
                const float c0 = acc[mi][ni][rr * 2], c1 = acc[mi][ni][rr * 2 + 1];
                const float2 bb = *(const float2*)(bias + col);
                if (MODE == 0) {
                    const int b_ = m >> 11, s = m & (SS - 1);
                    const int h = col >> 6, d = col & 63;
                    float* op = out + (((size_t)(b_ * HH + h)) * SS + s) * HD + d;
                    float2 o; o.x = c0 + bb.x; o.y = c1 + bb.y;
                    *(float2*)op = o;
                } else {
                    const size_t idx = (size_t)m * DD + col;
                    const float2 rv = *(const float2*)(res + idx);
                    float2 o; o.x = c0 + bb.x + rv.x; o.y = c1 + bb.y + rv.y;
                    *(float2*)(out + idx) = o;
                }
            }
        }
    }
}

// ---------------- suffix sums of V per (b,h): sfx[q] = sum_{k>q} v[k] ----------------
__global__ void sfxA_k(const float* __restrict__ vh, float* __restrict__ sfx,
                       float* __restrict__ ctot)
{
    const int bh = blockIdx.y, c = blockIdx.x, d = threadIdx.x;
    const size_t base = (size_t)bh*SS*HD + d;
    float acc = 0.f;
    for (int s = c*64 + 63; s >= c*64; s--) {
        sfx[base + (size_t)s*HD] = acc;
        acc += vh[base + (size_t)s*HD];
    }
    ctot[((size_t)bh*32 + c)*HD + d] = acc;
}

__global__ void sfxB_k(const float* __restrict__ ctot, float* __restrict__ csfx)
{
    const int bh = blockIdx.x, d = threadIdx.x;
    float acc = 0.f;
    for (int c = 31; c >= 0; c--) {
        csfx[((size_t)bh*32 + c)*HD + d] = acc;
        acc += ctot[((size_t)bh*32 + c)*HD + d];
    }
}

__global__ void sfxC_k(const float* __restrict__ csfx, float* __restrict__ sfx)
{
    const int bh = blockIdx.y, c = blockIdx.x, d = threadIdx.x;
    const float add = csfx[((size_t)bh*32 + c)*HD + d];
    const size_t base = (size_t)bh*SS*HD + d;
    for (int s = c*64; s < c*64 + 64; s++)
        sfx[base + (size_t)s*HD] += add;
}

// ---------------- attention: online softmax over causal keys, masked part folded in ----------------
__global__ __launch_bounds__(64)
void attn_k(const float* __restrict__ qh, const float* __restrict__ kh,
            const float* __restrict__ vh, const float* __restrict__ sfx,
            float* __restrict__ ctx)
{
    __shared__ float Ks[32][64];
    __shared__ float Vs[32][64];
    const int bh = blockIdx.y;
    const int q = blockIdx.x*64 + threadIdx.x;

    const float* qp = qh + ((size_t)bh*SS + q)*HD;
    float qr[64];
    #pragma unroll
    for (int i = 0; i < 16; i++) {
        float4 t = ((const float4*)qp)[i];
        qr[4*i+0] = t.x * 0.125f; qr[4*i+1] = t.y * 0.125f;   // fold 1/sqrt(HD)
        qr[4*i+2] = t.z * 0.125f; qr[4*i+3] = t.w * 0.125f;
    }
    float O[64];
    const float* sp = sfx + ((size_t)bh*SS + q)*HD;
    #pragma unroll
    for (int i = 0; i < 16; i++) {
        float4 t = ((const float4*)sp)[i];
        O[4*i+0] = t.x; O[4*i+1] = t.y; O[4*i+2] = t.z; O[4*i+3] = t.w;
    }
    float mv = 0.f;                      // masked entries contribute score 0
    float l  = (float)(SS - 1 - q);      // count of masked entries, each exp(0-0)=1

    const int qmax = blockIdx.x*64 + 63;
    const int ntiles = qmax/32 + 1;
    for (int kt = 0; kt < ntiles; kt++) {
        const int kbase = kt*32;
        const float* Kg = kh + ((size_t)bh*SS + kbase)*HD;
        const float* Vg = vh + ((size_t)bh*SS + kbase)*HD;
        #pragma unroll
        for (int j = 0; j < 8; j++) {
            int g = j*64 + threadIdx.x;     // 0..511 float4 granules
            int r = g >> 4, c = g & 15;
            ((float4*)Ks[r])[c] = ((const float4*)Kg)[g];
            ((float4*)Vs[r])[c] = ((const float4*)Vg)[g];
        }
        __syncthreads();
        int kend = q - kbase + 1;
        if (kend > 32) kend = 32;
        for (int kk = 0; kk < kend; kk++) {
            const float4* Kr = (const float4*)Ks[kk];
            float s0 = 0.f, s1 = 0.f, s2 = 0.f, s3 = 0.f;
            #pragma unroll
            for (int i = 0; i < 16; i++) {
                float4 kv = Kr[i];
                s0 += qr[4*i+0]*kv.x; s1 += qr[4*i+1]*kv.y;
                s2 += qr[4*i+2]*kv.z; s3 += qr[4*i+3]*kv.w;
            }
            float s = (s0 + s1) + (s2 + s3);
            if (s > mv) {                                  // rare (~ln(S) times total)
                float cf = __expf(mv - s);
                l *= cf;
                #pragma unroll
                for (int d = 0; d < 64; d++) O[d] *= cf;
                mv = s;
            }
            float p = __expf(s - mv);
            l += p;
            const float4* Vr = (const float4*)Vs[kk];
            #pragma unroll
            for (int i = 0; i < 16; i++) {
                float4 vv = Vr[i];
                O[4*i+0] += p*vv.x; O[4*i+1] += p*vv.y;
                O[4*i+2] += p*vv.z; O[4*i+3] += p*vv.w;
            }
        }
        __syncthreads();
    }

    const float inv = 1.f / l;
    const int b = bh / HH, h = bh % HH;
    float* op = ctx + ((size_t)(b*SS + q))*DD + h*HD;
    #pragma unroll
    for (int i = 0; i < 16; i++) {
        float4 t;
        t.x = O[4*i+0]*inv; t.y = O[4*i+1]*inv;
        t.z = O[4*i+2]*inv; t.w = O[4*i+3]*inv;
        ((float4*)op)[i] = t;
    }
}

// ---------------- LayerNorm (in place on d_out) ----------------
__global__ __launch_bounds__(256)
void ln_k(float* __restrict__ out, const float* __restrict__ gamma,
          const float* __restrict__ beta)
{
    const int row = blockIdx.x;
    float* p = out + (size_t)row*DD;
    const int t = threadIdx.x;
    float4 v = ((const float4*)p)[t];
    float sum = v.x + v.y + v.z + v.w;
    float sq  = v.x*v.x + v.y*v.y + v.z*v.z + v.w*v.w;
    #pragma unroll
    for (int o = 16; o > 0; o >>= 1) {
        sum += __shfl_xor_sync(0xffffffffu, sum, o);
        sq  += __shfl_xor_sync(0xffffffffu, sq,  o);
    }
    __shared__ float s1[8], s2[8];
    if ((t & 31) == 0) { s1[t >> 5] = sum; s2[t >> 5] = sq; }
    __syncthreads();
    __shared__ float smu, srstd;
    if (t < 32) {
        float a = (t < 8) ? s1[t] : 0.f;
        float b = (t < 8) ? s2[t] : 0.f;
        #pragma unroll
        for (int o = 4; o > 0; o >>= 1) {
            a += __shfl_xor_sync(0xffffffffu, a, o);
            b += __shfl_xor_sync(0xffffffffu, b, o);
        }
        if (t == 0) {
            float mu  = a * (1.f/DD);
            float var = b * (1.f/DD) - mu*mu;
            smu = mu;
            srstd = rsqrtf(var + 1e-5f);
        }
    }
    __syncthreads();
    const float mu = smu, rs = srstd;
    float4 g  = ((const float4*)gamma)[t];
    float4 be = ((const float4*)beta)[t];
    v.x = (v.x - mu)*rs*g.x + be.x;
    v.y = (v.y - mu)*rs*g.y + be.y;
    v.z = (v.z - mu)*rs*g.z + be.z;
    v.w = (v.w - mu)*rs*g.w + be.w;
    ((float4*)p)[t] = v;
}

// ---------------- launch ----------------
extern "C" void kernel_launch(void* const* d_in, const int* in_sizes, int n_in,
                              void* d_out, int out_size)
{
    const float* q     = (const float*)d_in[0];
    const float* k     = (const float*)d_in[1];
    const float* v     = (const float*)d_in[2];
    const float* Wq    = (const float*)d_in[3];
    const float* bq    = (const float*)d_in[4];
    const float* Wk    = (const float*)d_in[5];
    const float* bk    = (const float*)d_in[6];
    const float* Wv    = (const float*)d_in[7];
    const float* bv    = (const float*)d_in[8];
    const float* Wp    = (const float*)d_in[9];
    const float* bp    = (const float*)d_in[10];
    const float* gamma = (const float*)d_in[11];
    const float* beta  = (const float*)d_in[12];
    float* out = (float*)d_out;

    float *qh, *kh, *vh, *sfx, *ctx, *ctot, *csfx;
    __nv_bfloat16 *wth, *wtl, *ah, *al;
    cudaGetSymbolAddress((void**)&qh,  g_qh);
    cudaGetSymbolAddress((void**)&kh,  g_kh);
    cudaGetSymbolAddress((void**)&vh,  g_vh);
    cudaGetSymbolAddress((void**)&sfx, g_sfx);
    cudaGetSymbolAddress((void**)&ctx, g_ctx);
    cudaGetSymbolAddress((void**)&ctot, g_ctot);
    cudaGetSymbolAddress((void**)&csfx, g_csfx);
    cudaGetSymbolAddress((void**)&wth, g_wth);
    cudaGetSymbolAddress((void**)&wtl, g_wtl);
    cudaGetSymbolAddress((void**)&ah,  g_ah);
    cudaGetSymbolAddress((void**)&al,  g_al);

    // weights: transpose + hi/lo split
    dim3 cwg(32, 32), cwb(32, 32);
    convW_k<<<cwg, cwb>>>(Wq, wth + 0*(size_t)WSZ, wtl + 0*(size_t)WSZ);
    convW_k<<<cwg, cwb>>>(Wk, wth + 1*(size_t)WSZ, wtl + 1*(size_t)WSZ);
    convW_k<<<cwg, cwb>>>(Wv, wth + 2*(size_t)WSZ, wtl + 2*(size_t)WSZ);
    convW_k<<<cwg, cwb>>>(Wp, wth + 3*(size_t)WSZ, wtl + 3*(size_t)WSZ);

    dim3 gg(DD/128, MM/128);   // (8, 64)

    convA_k<<<2048, 1024>>>(q, ah, al);
    gemm_mma<0><<<gg, 256>>>(ah, al, wth + 0*(size_t)WSZ, wtl + 0*(size_t)WSZ, bq, nullptr, qh);
    convA_k<<<2048, 1024>>>(k, ah, al);
    gemm_mma<0><<<gg, 256>>>(ah, al, wth + 1*(size_t)WSZ, wtl + 1*(size_t)WSZ, bk, nullptr, kh);
    convA_k<<<2048, 1024>>>(v, ah, al);
    gemm_mma<0><<<gg, 256>>>(ah, al, wth + 2*(size_t)WSZ, wtl + 2*(size_t)WSZ, bv, nullptr, vh);

    dim3 gs(32, BB*HH);        // (32, 64)
    sfxA_k<<<gs, 64>>>(vh, sfx, ctot);
    sfxB_k<<<BB*HH, 64>>>(ctot, csfx);
    sfxC_k<<<gs, 64>>>(csfx, sfx);

    attn_k<<<dim3(SS/64, BB*HH), 64>>>(qh, kh, vh, sfx, ctx);

    convA_k<<<2048, 1024>>>(ctx, ah, al);
    gemm_mma<1><<<gg, 256>>>(ah, al, wth + 3*(size_t)WSZ, wtl + 3*(size_t)WSZ, bp, q, out);
    ln_k<<<MM, 256>>>(out, gamma, beta);
}

// round 8
// speedup vs baseline: 3.1294x; 2.0489x over previous
#include <cuda_runtime.h>
#include <cuda_bf16.h>
#include <cstdint>

#define BB 4
#define SS 2048
#define DD 1024
#define HH 16
#define HD 64
#define MM (BB*SS)   // 8192 rows
#define WSZ (1024*1024)
#define NBH (BB*HH)  // 64

// ---------------- scratch (no allocations allowed) ----------------
__device__ __nv_bfloat16 g_qhh[(size_t)NBH*SS*HD];  // Q heads hi (pre-scaled by 1/8)
__device__ __nv_bfloat16 g_qhl[(size_t)NBH*SS*HD];  // Q heads lo
__device__ __nv_bfloat16 g_khh[(size_t)NBH*SS*HD];
__device__ __nv_bfloat16 g_khl[(size_t)NBH*SS*HD];
__device__ float g_vh [(size_t)NBH*SS*HD];          // V heads fp32 [bh][s][d]
__device__ __nv_bfloat16 g_vth[(size_t)NBH*HD*SS];  // V^T hi [bh][d][s]
__device__ __nv_bfloat16 g_vtl[(size_t)NBH*HD*SS];  // V^T lo
__device__ float g_sfx[(size_t)NBH*SS*HD];          // suffix sums of V per head
__device__ float g_ctx[(size_t)MM*DD];              // attention output, [B,S,D]
__device__ float g_ctot[(size_t)NBH*32*HD];
__device__ float g_csfx[(size_t)NBH*32*HD];
__device__ __nv_bfloat16 g_wth[(size_t)4*WSZ];      // W^T hi, [N,K] per weight
__device__ __nv_bfloat16 g_wtl[(size_t)4*WSZ];      // W^T lo
__device__ __nv_bfloat16 g_ah [(size_t)MM*DD];      // activation hi (reused)
__device__ __nv_bfloat16 g_al [(size_t)MM*DD];      // activation lo

// ---------------- helpers ----------------
__device__ __forceinline__ uint32_t smem_u32(const void* p) {
    uint32_t a;
    asm("{ .reg .u64 t; cvta.to.shared.u64 t, %1; cvt.u32.u64 %0, t; }" : "=r"(a) : "l"(p));
    return a;
}
__device__ __forceinline__ void ldsm4(uint32_t* r, uint32_t addr) {
    asm volatile("ldmatrix.sync.aligned.m8n8.x4.shared.b16 {%0,%1,%2,%3}, [%4];"
        : "=r"(r[0]), "=r"(r[1]), "=r"(r[2]), "=r"(r[3]) : "r"(addr));
}
__device__ __forceinline__ void mma16816(float* c, const uint32_t* a, const uint32_t* b) {
    asm volatile("mma.sync.aligned.m16n8k16.row.col.f32.bf16.bf16.f32 "
        "{%0,%1,%2,%3}, {%4,%5,%6,%7}, {%8,%9}, {%0,%1,%2,%3};"
        : "+f"(c[0]), "+f"(c[1]), "+f"(c[2]), "+f"(c[3])
        : "r"(a[0]), "r"(a[1]), "r"(a[2]), "r"(a[3]), "r"(b[0]), "r"(b[1]));
}
// split a pair of floats into packed bf16 hi and lo (x in low half)
__device__ __forceinline__ void split2(float x, float y, uint32_t& h, uint32_t& l) {
    __nv_bfloat162 hb = __floats2bfloat162_rn(x, y);
    float hx = __bfloat162float(hb.x), hy = __bfloat162float(hb.y);
    __nv_bfloat162 lb = __floats2bfloat162_rn(x - hx, y - hy);
    h = *(uint32_t*)&hb;
    l = *(uint32_t*)&lb;
}

// ---------------- fp32 -> bf16 hi/lo split (elementwise, float4) ----------------
__global__ __launch_bounds__(1024)
void convA_k(const float* __restrict__ A, __nv_bfloat16* __restrict__ hi,
             __nv_bfloat16* __restrict__ lo)
{
    size_t i = (size_t)blockIdx.x * blockDim.x + threadIdx.x;   // one float4 each
    float4 v = ((const float4*)A)[i];
    union { __nv_bfloat16 b[4]; uint2 u; } ph, pl;
    #pragma unroll
    for (int j = 0; j < 4; j++) {
        float x = (&v.x)[j];
        __nv_bfloat16 h = __float2bfloat16(x);
        ph.b[j] = h;
        pl.b[j] = __float2bfloat16(x - __bfloat162float(h));
    }
    ((uint2*)hi)[i] = ph.u;
    ((uint2*)lo)[i] = pl.u;
}

// ---------------- W [K,N] fp32 -> W^T [N,K] bf16 hi/lo ----------------
__global__ __launch_bounds__(1024)
void convW_k(const float* __restrict__ W, __nv_bfloat16* __restrict__ hi,
             __nv_bfloat16* __restrict__ lo)
{
    __shared__ float t[32][33];
    const int k0 = blockIdx.y * 32, n0 = blockIdx.x * 32;
    t[threadIdx.y][threadIdx.x] = W[(size_t)(k0 + threadIdx.y) * DD + n0 + threadIdx.x];
    __syncthreads();
    float v = t[threadIdx.x][threadIdx.y];   // = W[k0+tx][n0+ty]
    size_t o = (size_t)(n0 + threadIdx.y) * DD + k0 + threadIdx.x;
    __nv_bfloat16 h = __float2bfloat16(v);
    hi[o] = h;
    lo[o] = __float2bfloat16(v - __bfloat162float(h));
}

// ---------------- V fp32 [bh][s][d] -> V^T bf16 hi/lo [bh][d][s] ----------------
__global__ __launch_bounds__(1024)
void convVT_k(const float* __restrict__ vh, __nv_bfloat16* __restrict__ vth,
              __nv_bfloat16* __restrict__ vtl)
{
    __shared__ float t[32][33];
    const int bh = blockIdx.z;
    const int s0 = blockIdx.x * 32, d0 = blockIdx.y * 32;
    t[threadIdx.y][threadIdx.x] =
        vh[((size_t)bh * SS + s0 + threadIdx.y) * HD + d0 + threadIdx.x];
    __syncthreads();
    float v = t[threadIdx.x][threadIdx.y];   // = vh[s0+tx][d0+ty]
    size_t o = ((size_t)bh * HD + d0 + threadIdx.y) * SS + s0 + threadIdx.x;
    __nv_bfloat16 h = __float2bfloat16(v);
    vth[o] = h;
    vtl[o] = __float2bfloat16(v - __bfloat162float(h));
}

// ---------------- mma.sync GEMM: D = Ahi@Bhi + Ahi@Blo + Alo@Bhi ----------------
// MODE 0: bf16 hi/lo out to head layout [bh][s][d], scaled.
// MODE 1: fp32 [M,N] + residual. MODE 2: fp32 head layout.
template<int MODE>
__global__ __launch_bounds__(256)
void gemm_mma(const __nv_bfloat16* __restrict__ Ah, const __nv_bfloat16* __restrict__ Al,
              const __nv_bfloat16* __restrict__ Bh, const __nv_bfloat16* __restrict__ Bl,
              const float* __restrict__ bias, const float* __restrict__ res,
              float* __restrict__ outf, __nv_bfloat16* __restrict__ outh,
              __nv_bfloat16* __restrict__ outl, float scale)
{
    __shared__ alignas(128) __nv_bfloat16 sAh[128*32];
    __shared__ alignas(128) __nv_bfloat16 sAl[128*32];
    __shared__ alignas(128) __nv_bfloat16 sBh[128*32];
    __shared__ alignas(128) __nv_bfloat16 sBl[128*32];

    const int tid = threadIdx.x, lane = tid & 31, wid = tid >> 5;
    const int wm = (wid & 1) * 64, wn = (wid >> 1) * 32;
    const int m0 = blockIdx.y * 128, n0 = blockIdx.x * 128;

    const int strow = tid >> 1;
    const int stc0  = (tid & 1) * 2;
    const int stsw  = (strow >> 1) & 3;
    const int ss0   = strow * 4 + (stc0 ^ stsw);
    const int ss1   = strow * 4 + ((stc0 + 1) ^ stsw);
    const __nv_bfloat16* pAh = Ah + (size_t)(m0 + strow) * DD + stc0 * 8;
    const __nv_bfloat16* pAl = Al + (size_t)(m0 + strow) * DD + stc0 * 8;
    const __nv_bfloat16* pBh = Bh + (size_t)(n0 + strow) * DD + stc0 * 8;
    const __nv_bfloat16* pBl = Bl + (size_t)(n0 + strow) * DD + stc0 * 8;
    uint4* s4Ah = (uint4*)sAh; uint4* s4Al = (uint4*)sAl;
    uint4* s4Bh = (uint4*)sBh; uint4* s4Bl = (uint4*)sBl;

    const uint32_t aAh = smem_u32(sAh), aAl = smem_u32(sAl);
    const uint32_t aBh = smem_u32(sBh), aBl = smem_u32(sBl);
    const int la15 = lane & 15;
    const uint32_t Aoff = (uint32_t)(wm + la15) * 64;
    const int swA = (la15 >> 1) & 3;
    const uint32_t cA0 = (uint32_t)(((lane >> 4)     ) ^ swA) * 16;
    const uint32_t cA1 = (uint32_t)((2 + (lane >> 4)) ^ swA) * 16;
    const int la7 = lane & 7;
    const uint32_t Boff = (uint32_t)(wn + la7 + ((lane >> 4) << 3)) * 64;
    const int swB = (la7 >> 1) & 3;
    const uint32_t cB0 = (uint32_t)((((lane >> 3) & 1)    ) ^ swB) * 16;
    const uint32_t cB1 = (uint32_t)((2 + ((lane >> 3) & 1)) ^ swB) * 16;

    float acc[4][4][4];
    #pragma unroll
    for (int mi = 0; mi < 4; mi++)
        #pragma unroll
        for (int ni = 0; ni < 4; ni++)
            #pragma unroll
            for (int r = 0; r < 4; r++) acc[mi][ni][r] = 0.f;

    uint4 vah0, vah1, val0, val1, vbh0, vbh1, vbl0, vbl1;
    vah0 = *(const uint4*)(pAh);      vah1 = *(const uint4*)(pAh + 8);
    val0 = *(const uint4*)(pAl);      val1 = *(const uint4*)(pAl + 8);
    vbh0 = *(const uint4*)(pBh);      vbh1 = *(const uint4*)(pBh + 8);
    vbl0 = *(const uint4*)(pBl);      vbl1 = *(const uint4*)(pBl + 8);

    for (int kc = 0; kc < 32; kc++) {
        s4Ah[ss0] = vah0; s4Ah[ss1] = vah1;
        s4Al[ss0] = val0; s4Al[ss1] = val1;
        s4Bh[ss0] = vbh0; s4Bh[ss1] = vbh1;
        s4Bl[ss0] = vbl0; s4Bl[ss1] = vbl1;
        __syncthreads();

        if (kc < 31) {
            const int k0 = (kc + 1) * 32;
            vah0 = *(const uint4*)(pAh + k0);  vah1 = *(const uint4*)(pAh + k0 + 8);
            val0 = *(const uint4*)(pAl + k0);  val1 = *(const uint4*)(pAl + k0 + 8);
            vbh0 = *(const uint4*)(pBh + k0);  vbh1 = *(const uint4*)(pBh + k0 + 8);
            vbl0 = *(const uint4*)(pBl + k0);  vbl1 = *(const uint4*)(pBl + k0 + 8);
        }

        #pragma unroll
        for (int ks = 0; ks < 2; ks++) {
            const uint32_t cA = ks ? cA1 : cA0;
            const uint32_t cB = ks ? cB1 : cB0;
            uint32_t a[4][4], a2[4][4], b[2][4], b2[2][4];
            #pragma unroll
            for (int mi = 0; mi < 4; mi++) ldsm4(a[mi], aAh + Aoff + mi * 1024 + cA);
            #pragma unroll
            for (int nt = 0; nt < 2; nt++) ldsm4(b[nt], aBh + Boff + nt * 1024 + cB);
            #pragma unroll
            for (int mi = 0; mi < 4; mi++)
                #pragma unroll
                for (int ni = 0; ni < 4; ni++)
                    mma16816(acc[mi][ni], a[mi], &b[ni >> 1][(ni & 1) * 2]);   // hi*hi
            #pragma unroll
            for (int nt = 0; nt < 2; nt++) ldsm4(b2[nt], aBl + Boff + nt * 1024 + cB);
            #pragma unroll
            for (int mi = 0; mi < 4; mi++)
                #pragma unroll
                for (int ni = 0; ni < 4; ni++)
                    mma16816(acc[mi][ni], a[mi], &b2[ni >> 1][(ni & 1) * 2]);  // hi*lo
            #pragma unroll
            for (int mi = 0; mi < 4; mi++) ldsm4(a2[mi], aAl + Aoff + mi * 1024 + cA);
            #pragma unroll
            for (int mi = 0; mi < 4; mi++)
                #pragma unroll
                for (int ni = 0; ni < 4; ni++)
                    mma16816(acc[mi][ni], a2[mi], &b[ni >> 1][(ni & 1) * 2]);  // lo*hi
        }
        __syncthreads();
    }

    // ---- epilogue ----
    const int gid = lane >> 2, tig = (lane & 3) * 2;
    #pragma unroll
    for (int mi = 0; mi < 4; mi++) {
        #pragma unroll
        for (int rr = 0; rr < 2; rr++) {
            const int m = m0 + wm + mi * 16 + gid + rr * 8;
            #pragma unroll
            for (int ni = 0; ni < 4; ni++) {
                const int col = n0 + wn + ni * 8 + tig;
                const float c0 = acc[mi][ni][rr * 2], c1 = acc[mi][ni][rr * 2 + 1];
                const float2 bb = *(const float2*)(bias + col);
                if (MODE == 0) {
                    const int b_ = m >> 11, s = m & (SS - 1);
                    const int h = col >> 6, d = col & 63;
                    const float v0 = (c0 + bb.x) * scale;
                    const float v1 = (c1 + bb.y) * scale;
                    uint32_t hh, ll;
                    split2(v0, v1, hh, ll);
                    const size_t base = (((size_t)(b_ * HH + h)) * SS + s) * HD + d;
                    *(uint32_t*)(outh + base) = hh;
                    *(uint32_t*)(outl + base) = ll;
                } else if (MODE == 2) {
                    const int b_ = m >> 11, s = m & (SS - 1);
                    const int h = col >> 6, d = col & 63;
                    float* op = outf + (((size_t)(b_ * HH + h)) * SS + s) * HD + d;
                    float2 o; o.x = c0 + bb.x; o.y = c1 + bb.y;
                    *(float2*)op = o;
                } else {
                    const size_t idx = (size_t)m * DD + col;
                    const float2 rv = *(const float2*)(res + idx);
                    float2 o; o.x = c0 + bb.x + rv.x; o.y = c1 + bb.y + rv.y;
                    *(float2*)(outf + idx) = o;
                }
            }
        }
    }
}

// ---------------- suffix sums of V per (b,h): sfx[q] = sum_{k>q} v[k] ----------------
__global__ void sfxA_k(const float* __restrict__ vh, float* __restrict__ sfx,
                       float* __restrict__ ctot)
{
    const int bh = blockIdx.y, c = blockIdx.x, d = threadIdx.x;
    const size_t base = (size_t)bh*SS*HD + d;
    float acc = 0.f;
    for (int s = c*64 + 63; s >= c*64; s--) {
        sfx[base + (size_t)s*HD] = acc;
        acc += vh[base + (size_t)s*HD];
    }
    ctot[((size_t)bh*32 + c)*HD + d] = acc;
}

__global__ void sfxB_k(const float* __restrict__ ctot, float* __restrict__ csfx)
{
    const int bh = blockIdx.x, d = threadIdx.x;
    float acc = 0.f;
    for (int c = 31; c >= 0; c--) {
        csfx[((size_t)bh*32 + c)*HD + d] = acc;
        acc += ctot[((size_t)bh*32 + c)*HD + d];
    }
}

__global__ void sfxC_k(const float* __restrict__ csfx, float* __restrict__ sfx)
{
    const int bh = blockIdx.y, c = blockIdx.x, d = threadIdx.x;
    const float add = csfx[((size_t)bh*32 + c)*HD + d];
    const size_t base = (size_t)bh*SS*HD + d;
    for (int s = c*64; s < c*64 + 64; s++)
        sfx[base + (size_t)s*HD] += add;
}

// ---------------- flash attention with mma.sync, hi/lo splits, masked-part fixup ----
// CTA: 64 queries x one (b,h). 128 threads, 4 warps x m16.
__global__ __launch_bounds__(128)
void attn_mma(const __nv_bfloat16* __restrict__ qhh, const __nv_bfloat16* __restrict__ qhl,
              const __nv_bfloat16* __restrict__ khh, const __nv_bfloat16* __restrict__ khl,
              const __nv_bfloat16* __restrict__ vth, const __nv_bfloat16* __restrict__ vtl,
              const float* __restrict__ sfx, float* __restrict__ ctx)
{
    // 6 tiles of 64x64 bf16 = 48KB exactly
    __shared__ __align__(16) __nv_bfloat16 sm[6*4096];
    __nv_bfloat16 *sQh = sm,          *sQl = sm + 4096;
    __nv_bfloat16 *sKh = sm + 8192,   *sKl = sm + 12288;
    __nv_bfloat16 *sVh = sm + 16384,  *sVl = sm + 20480;

    const int tid = threadIdx.x, lane = tid & 31, wid = tid >> 5;
    const int qblk = (int)gridDim.x - 1 - (int)blockIdx.x;   // heavy CTAs first
    const int bh = blockIdx.y;
    const int q0 = qblk * 64;
    const int wm = wid * 16;

    // ---- load Q tile (hi/lo), swizzled ----
    {
        const __nv_bfloat16* gh = qhh + ((size_t)bh * SS + q0) * HD;
        const __nv_bfloat16* gl = qhl + ((size_t)bh * SS + q0) * HD;
        #pragma unroll
        for (int it = 0; it < 4; it++) {
            const int idx = it * 128 + tid;
            const int r = idx >> 3, c = idx & 7;
            const int sc = c ^ (r & 7);
            ((uint4*)sQh)[r * 8 + sc] = ((const uint4*)(gh + (size_t)r * HD))[c];
            ((uint4*)sQl)[r * 8 + sc] = ((const uint4*)(gl + (size_t)r * HD))[c];
        }
    }
    __syncthreads();

    // ---- Q fragments (held for whole kernel) ----
    uint32_t qfh[4][4], qfl[4][4];
    {
        const uint32_t aQh = smem_u32(sQh), aQl = smem_u32(sQl);
        const int row = wm + (lane & 15);
        const int swr = row & 7;
        const uint32_t rb = (uint32_t)row * 128;
        #pragma unroll
        for (int ks = 0; ks < 4; ks++) {
            const uint32_t c = (uint32_t)((2 * ks + (lane >> 4)) ^ swr) * 16;
            ldsm4(qfh[ks], aQh + rb + c);
            ldsm4(qfl[ks], aQl + rb + c);
        }
    }

    // B-side ldsm addressing (shared by K and V^T tiles; both [n][64] rows of 128B)
    const int brow = (lane & 7) + ((lane >> 4) << 3);   // 0..15
    const int bsw  = brow & 7;
    const int bkb  = (lane >> 3) & 1;
    const uint32_t aKh = smem_u32(sKh), aKl = smem_u32(sKl);
    const uint32_t aVh = smem_u32(sVh), aVl = smem_u32(sVl);

    float O[8][4];
    #pragma unroll
    for (int nb = 0; nb < 8; nb++)
        #pragma unroll
        for (int r = 0; r < 4; r++) O[nb][r] = 0.f;
    float m0 = 0.f, m1 = 0.f, l0 = 0.f, l1 = 0.f;
    const int g = lane >> 2, tig = (lane & 3) * 2;
    const int r0 = q0 + wm + g, r1 = r0 + 8;

    const __nv_bfloat16* Kh0 = khh + (size_t)bh * SS * HD;
    const __nv_bfloat16* Kl0 = khl + (size_t)bh * SS * HD;
    const __nv_bfloat16* Vh0 = vth + (size_t)bh * HD * SS;
    const __nv_bfloat16* Vl0 = vtl + (size_t)bh * HD * SS;

    for (int kt = 0; kt <= qblk; kt++) {
        const int kbase = kt * 64;
        __syncthreads();
        // ---- fill K (rows=key) and V^T (rows=d) tiles ----
        #pragma unroll
        for (int it = 0; it < 4; it++) {
            const int idx = it * 128 + tid;
            const int r = idx >> 3, c = idx & 7;
            const int sc = r * 8 + (c ^ (r & 7));
            ((uint4*)sKh)[sc] = ((const uint4*)(Kh0 + (size_t)(kbase + r) * HD))[c];
            ((uint4*)sKl)[sc] = ((const uint4*)(Kl0 + (size_t)(kbase + r) * HD))[c];
            ((uint4*)sVh)[sc] = ((const uint4*)(Vh0 + (size_t)r * SS + kbase))[c];
            ((uint4*)sVl)[sc] = ((const uint4*)(Vl0 + (size_t)r * SS + kbase))[c];
        }
        __syncthreads();

        // ---- S = Q K^T (3-pass split) ----
        float sacc[8][4];
        #pragma unroll
        for (int nb = 0; nb < 8; nb++)
            #pragma unroll
            for (int r = 0; r < 4; r++) sacc[nb][r] = 0.f;

        #pragma unroll
        for (int ks = 0; ks < 4; ks++) {
            const uint32_t coff = (uint32_t)((2 * ks + bkb) ^ bsw) * 16;
            uint32_t bfr[4][4];
            #pragma unroll
            for (int nt = 0; nt < 4; nt++)
                ldsm4(bfr[nt], aKh + (uint32_t)(nt * 16 + brow) * 128 + coff);
            #pragma unroll
            for (int nb = 0; nb < 8; nb++)
                mma16816(sacc[nb], qfh[ks], &bfr[nb >> 1][(nb & 1) * 2]);   // Qhi*Khi
            #pragma unroll
            for (int nb = 0; nb < 8; nb++)
                mma16816(sacc[nb], qfl[ks], &bfr[nb >> 1][(nb & 1) * 2]);   // Qlo*Khi
            #pragma unroll
            for (int nt = 0; nt < 4; nt++)
                ldsm4(bfr[nt], aKl + (uint32_t)(nt * 16 + brow) * 128 + coff);
            #pragma unroll
            for (int nb = 0; nb < 8; nb++)
                mma16816(sacc[nb], qfh[ks], &bfr[nb >> 1][(nb & 1) * 2]);   // Qhi*Klo
        }

        // ---- causal mask (diagonal tile only) ----
        if (kt == qblk) {
            #pragma unroll
            for (int nb = 0; nb < 8; nb++) {
                const int key = kbase + nb * 8 + tig;
                if (key     > r0) sacc[nb][0] = -1e30f;
                if (key + 1 > r0) sacc[nb][1] = -1e30f;
                if (key     > r1) sacc[nb][2] = -1e30f;
                if (key + 1 > r1) sacc[nb][3] = -1e30f;
            }
        }

        // ---- online softmax ----
        float mx0 = -1e30f, mx1 = -1e30f;
        #pragma unroll
        for (int nb = 0; nb < 8; nb++) {
            mx0 = fmaxf(mx0, fmaxf(sacc[nb][0], sacc[nb][1]));
            mx1 = fmaxf(mx1, fmaxf(sacc[nb][2], sacc[nb][3]));
        }
        mx0 = fmaxf(mx0, __shfl_xor_sync(0xffffffffu, mx0, 1));
        mx0 = fmaxf(mx0, __shfl_xor_sync(0xffffffffu, mx0, 2));
        mx1 = fmaxf(mx1, __shfl_xor_sync(0xffffffffu, mx1, 1));
        mx1 = fmaxf(mx1, __shfl_xor_sync(0xffffffffu, mx1, 2));
        const float mn0 = fmaxf(m0, mx0), mn1 = fmaxf(m1, mx1);
        const float cf0 = __expf(m0 - mn0), cf1 = __expf(m1 - mn1);
        m0 = mn0; m1 = mn1;
        l0 *= cf0; l1 *= cf1;
        #pragma unroll
        for (int nb = 0; nb < 8; nb++) {
            O[nb][0] *= cf0; O[nb][1] *= cf0;
            O[nb][2] *= cf1; O[nb][3] *= cf1;
        }
        float ps0 = 0.f, ps1 = 0.f;
        #pragma unroll
        for (int nb = 0; nb < 8; nb++) {
            const float p0 = __expf(sacc[nb][0] - m0);
            const float p1 = __expf(sacc[nb][1] - m0);
            const float p2 = __expf(sacc[nb][2] - m1);
            const float p3 = __expf(sacc[nb][3] - m1);
            sacc[nb][0] = p0; sacc[nb][1] = p1; sacc[nb][2] = p2; sacc[nb][3] = p3;
            ps0 += p0 + p1; ps1 += p2 + p3;
        }
        ps0 += __shfl_xor_sync(0xffffffffu, ps0, 1);
        ps0 += __shfl_xor_sync(0xffffffffu, ps0, 2);
        ps1 += __shfl_xor_sync(0xffffffffu, ps1, 1);
        ps1 += __shfl_xor_sync(0xffffffffu, ps1, 2);
        l0 += ps0; l1 += ps1;

        // ---- O += P V (3-pass split; P frags straight from registers) ----
        #pragma unroll
        for (int ks = 0; ks < 4; ks++) {
            uint32_t pah[4], pal[4];
            split2(sacc[2*ks  ][0], sacc[2*ks  ][1], pah[0], pal[0]);
            split2(sacc[2*ks  ][2], sacc[2*ks  ][3], pah[1], pal[1]);
            split2(sacc[2*ks+1][0], sacc[2*ks+1][1], pah[2], pal[2]);
            split2(sacc[2*ks+1][2], sacc[2*ks+1][3], pah[3], pal[3]);
            const uint32_t coff = (uint32_t)((2 * ks + bkb) ^ bsw) * 16;
            uint32_t bfr[4][4];
            #pragma unroll
            for (int nt = 0; nt < 4; nt++)
                ldsm4(bfr[nt], aVh + (uint32_t)(nt * 16 + brow) * 128 + coff);
            #pragma unroll
            for (int nb = 0; nb < 8; nb++)
                mma16816(O[nb], pah, &bfr[nb >> 1][(nb & 1) * 2]);   // Phi*Vhi
            #pragma unroll
            for (int nb = 0; nb < 8; nb++)
                mma16816(O[nb], pal, &bfr[nb >> 1][(nb & 1) * 2]);   // Plo*Vhi
            #pragma unroll
            for (int nt = 0; nt < 4; nt++)
                ldsm4(bfr[nt], aVl + (uint32_t)(nt * 16 + brow) * 128 + coff);
            #pragma unroll
            for (int nb = 0; nb < 8; nb++)
                mma16816(O[nb], pah, &bfr[nb >> 1][(nb & 1) * 2]);   // Phi*Vlo
        }
    }

    // ---- finalize: fold masked (post-causal) contribution, normalize, write ----
    const float em0 = __expf(-m0), em1 = __expf(-m1);
    const float lt0 = l0 + (float)(SS - 1 - r0) * em0;
    const float lt1 = l1 + (float)(SS - 1 - r1) * em1;
    const float inv0 = 1.f / lt0, inv1 = 1.f / lt1;
    const int b_ = bh >> 4, h = bh & 15;
    const float* sp0 = sfx + ((size_t)bh * SS + r0) * HD;
    const float* sp1 = sfx + ((size_t)bh * SS + r1) * HD;
    float* o0 = ctx + ((size_t)(b_ * SS + r0)) * DD + h * HD;
    float* o1 = ctx + ((size_t)(b_ * SS + r1)) * DD + h * HD;
    #pragma unroll
    for (int nb = 0; nb < 8; nb++) {
        const int d = nb * 8 + tig;
        const float2 sv0 = *(const float2*)(sp0 + d);
        const float2 sv1 = *(const float2*)(sp1 + d);
        float2 w0, w1;
        w0.x = (O[nb][0] + em0 * sv0.x) * inv0;
        w0.y = (O[nb][1] + em0 * sv0.y) * inv0;
        w1.x = (O[nb][2] + em1 * sv1.x) * inv1;
        w1.y = (O[nb][3] + em1 * sv1.y) * inv1;
        *(float2*)(o0 + d) = w0;
        *(float2*)(o1 + d) = w1;
    }
}

// ---------------- LayerNorm (in place on d_out) ----------------
__global__ __launch_bounds__(256)
void ln_k(float* __restrict__ out, const float* __restrict__ gamma,
          const float* __restrict__ beta)
{
    const int row = blockIdx.x;
    float* p = out + (size_t)row*DD;
    const int t = threadIdx.x;
    float4 v = ((const float4*)p)[t];
    float sum = v.x + v.y + v.z + v.w;
    float sq  = v.x*v.x + v.y*v.y + v.z*v.z + v.w*v.w;
    #pragma unroll
    for (int o = 16; o > 0; o >>= 1) {
        sum += __shfl_xor_sync(0xffffffffu, sum, o);
        sq  += __shfl_xor_sync(0xffffffffu, sq,  o);
    }
    __shared__ float s1[8], s2[8];
    if ((t & 31) == 0) { s1[t >> 5] = sum; s2[t >> 5] = sq; }
    __syncthreads();
    __shared__ float smu, srstd;
    if (t < 32) {
        float a = (t < 8) ? s1[t] : 0.f;
        float b = (t < 8) ? s2[t] : 0.f;
        #pragma unroll
        for (int o = 4; o > 0; o >>= 1) {
            a += __shfl_xor_sync(0xffffffffu, a, o);
            b += __shfl_xor_sync(0xffffffffu, b, o);
        }
        if (t == 0) {
            float mu  = a * (1.f/DD);
            float var = b * (1.f/DD) - mu*mu;
            smu = mu;
            srstd = rsqrtf(var + 1e-5f);
        }
    }
    __syncthreads();
    const float mu = smu, rs = srstd;
    float4 gm = ((const float4*)gamma)[t];
    float4 be = ((const float4*)beta)[t];
    v.x = (v.x - mu)*rs*gm.x + be.x;
    v.y = (v.y - mu)*rs*gm.y + be.y;
    v.z = (v.z - mu)*rs*gm.z + be.z;
    v.w = (v.w - mu)*rs*gm.w + be.w;
    ((float4*)p)[t] = v;
}

// ---------------- launch ----------------
extern "C" void kernel_launch(void* const* d_in, const int* in_sizes, int n_in,
                              void* d_out, int out_size)
{
    const float* q     = (const float*)d_in[0];
    const float* k     = (const float*)d_in[1];
    const float* v     = (const float*)d_in[2];
    const float* Wq    = (const float*)d_in[3];
    const float* bq    = (const float*)d_in[4];
    const float* Wk    = (const float*)d_in[5];
    const float* bk    = (const float*)d_in[6];
    const float* Wv    = (const float*)d_in[7];
    const float* bv    = (const float*)d_in[8];
    const float* Wp    = (const float*)d_in[9];
    const float* bp    = (const float*)d_in[10];
    const float* gamma = (const float*)d_in[11];
    const float* beta  = (const float*)d_in[12];
    float* out = (float*)d_out;

    float *vh, *sfx, *ctx, *ctot, *csfx;
    __nv_bfloat16 *qhh, *qhl, *khh, *khl, *vth, *vtl, *wth, *wtl, *ah, *al;
    cudaGetSymbolAddress((void**)&qhh, g_qhh);
    cudaGetSymbolAddress((void**)&qhl, g_qhl);
    cudaGetSymbolAddress((void**)&khh, g_khh);
    cudaGetSymbolAddress((void**)&khl, g_khl);
    cudaGetSymbolAddress((void**)&vh,  g_vh);
    cudaGetSymbolAddress((void**)&vth, g_vth);
    cudaGetSymbolAddress((void**)&vtl, g_vtl);
    cudaGetSymbolAddress((void**)&sfx, g_sfx);
    cudaGetSymbolAddress((void**)&ctx, g_ctx);
    cudaGetSymbolAddress((void**)&ctot, g_ctot);
    cudaGetSymbolAddress((void**)&csfx, g_csfx);
    cudaGetSymbolAddress((void**)&wth, g_wth);
    cudaGetSymbolAddress((void**)&wtl, g_wtl);
    cudaGetSymbolAddress((void**)&ah,  g_ah);
    cudaGetSymbolAddress((void**)&al,  g_al);

    // weights: transpose + hi/lo split
    dim3 cwg(32, 32), cwb(32, 32);
    convW_k<<<cwg, cwb>>>(Wq, wth + 0*(size_t)WSZ, wtl + 0*(size_t)WSZ);
    convW_k<<<cwg, cwb>>>(Wk, wth + 1*(size_t)WSZ, wtl + 1*(size_t)WSZ);
    convW_k<<<cwg, cwb>>>(Wv, wth + 2*(size_t)WSZ, wtl + 2*(size_t)WSZ);
    convW_k<<<cwg, cwb>>>(Wp, wth + 3*(size_t)WSZ, wtl + 3*(size_t)WSZ);

    dim3 gg(DD/128, MM/128);   // (8, 64)

    // Q: bf16 hi/lo, pre-scaled by 1/sqrt(HD)
    convA_k<<<2048, 1024>>>(q, ah, al);
    gemm_mma<0><<<gg, 256>>>(ah, al, wth + 0*(size_t)WSZ, wtl + 0*(size_t)WSZ, bq,
                             nullptr, nullptr, qhh, qhl, 0.125f);
    // K: bf16 hi/lo
    convA_k<<<2048, 1024>>>(k, ah, al);
    gemm_mma<0><<<gg, 256>>>(ah, al, wth + 1*(size_t)WSZ, wtl + 1*(size_t)WSZ, bk,
                             nullptr, nullptr, khh, khl, 1.0f);
    // V: fp32 head layout (for suffix sums) + transposed bf16 hi/lo
    convA_k<<<2048, 1024>>>(v, ah, al);
    gemm_mma<2><<<gg, 256>>>(ah, al, wth + 2*(size_t)WSZ, wtl + 2*(size_t)WSZ, bv,
                             nullptr, vh, nullptr, nullptr, 1.0f);

    dim3 gs(32, NBH);
    sfxA_k<<<gs, 64>>>(vh, sfx, ctot);
    sfxB_k<<<NBH, 64>>>(ctot, csfx);
    sfxC_k<<<gs, 64>>>(csfx, sfx);
    convVT_k<<<dim3(SS/32, HD/32, NBH), dim3(32, 32)>>>(vh, vth, vtl);

    attn_mma<<<dim3(SS/64, NBH), 128>>>(qhh, qhl, khh, khl, vth, vtl, sfx, ctx);

    convA_k<<<2048, 1024>>>(ctx, ah, al);
    gemm_mma<1><<<gg, 256>>>(ah, al, wth + 3*(size_t)WSZ, wtl + 3*(size_t)WSZ, bp,
                             q, out, nullptr, nullptr, 1.0f);
    ln_k<<<MM, 256>>>(out, gamma, beta);
}

// round 12
// speedup vs baseline: 3.1703x; 1.0131x over previous
#include <cuda_runtime.h>
#include <cuda_bf16.h>
#include <cstdint>

#define BB 4
#define SS 2048
#define DD 1024
#define HH 16
#define HD 64
#define MM (BB*SS)   // 8192 rows
#define WSZ (1024*1024)
#define NBH (BB*HH)  // 64

// ---------------- scratch (no allocations allowed) ----------------
__device__ __nv_bfloat16 g_qhh[(size_t)NBH*SS*HD];  // Q heads hi (pre-scaled by 1/8)
__device__ __nv_bfloat16 g_qhl[(size_t)NBH*SS*HD];  // Q heads lo
__device__ __nv_bfloat16 g_khh[(size_t)NBH*SS*HD];
__device__ __nv_bfloat16 g_khl[(size_t)NBH*SS*HD];
__device__ float g_vh [(size_t)NBH*SS*HD];          // V heads fp32 [bh][s][d]
__device__ __nv_bfloat16 g_vth[(size_t)NBH*HD*SS];  // V^T hi [bh][d][s]
__device__ __nv_bfloat16 g_vtl[(size_t)NBH*HD*SS];  // V^T lo
__device__ float g_sfx[(size_t)NBH*SS*HD];          // suffix sums of V per head
__device__ float g_ctx[(size_t)MM*DD];              // attention output, [B,S,D]
__device__ float g_ctot[(size_t)NBH*32*HD];
__device__ float g_csfx[(size_t)NBH*32*HD];
__device__ __nv_bfloat16 g_wth[(size_t)4*WSZ];      // W^T hi, [N,K] per weight
__device__ __nv_bfloat16 g_wtl[(size_t)4*WSZ];      // W^T lo
__device__ __nv_bfloat16 g_ah [(size_t)MM*DD];      // activation hi (reused)
__device__ __nv_bfloat16 g_al [(size_t)MM*DD];      // activation lo

// ---------------- helpers ----------------
__device__ __forceinline__ uint32_t smem_u32(const void* p) {
    uint32_t a;
    asm("{ .reg .u64 t; cvta.to.shared.u64 t, %1; cvt.u32.u64 %0, t; }" : "=r"(a) : "l"(p));
    return a;
}
__device__ __forceinline__ void ldsm4(uint32_t* r, uint32_t addr) {
    asm volatile("ldmatrix.sync.aligned.m8n8.x4.shared.b16 {%0,%1,%2,%3}, [%4];"
        : "=r"(r[0]), "=r"(r[1]), "=r"(r[2]), "=r"(r[3]) : "r"(addr));
}
__device__ __forceinline__ void mma16816(float* c, const uint32_t* a, const uint32_t* b) {
    asm volatile("mma.sync.aligned.m16n8k16.row.col.f32.bf16.bf16.f32 "
        "{%0,%1,%2,%3}, {%4,%5,%6,%7}, {%8,%9}, {%0,%1,%2,%3};"
        : "+f"(c[0]), "+f"(c[1]), "+f"(c[2]), "+f"(c[3])
        : "r"(a[0]), "r"(a[1]), "r"(a[2]), "r"(a[3]), "r"(b[0]), "r"(b[1]));
}
__device__ __forceinline__ void cp16(uint32_t dst, const void* src) {
    asm volatile("cp.async.cg.shared.global [%0], [%1], 16;" :: "r"(dst), "l"(src));
}
#define CP_COMMIT() asm volatile("cp.async.commit_group;" ::: "memory")
#define CP_WAIT0()  asm volatile("cp.async.wait_group 0;" ::: "memory")

// split a pair of floats into packed bf16 hi and lo (x in low half)
__device__ __forceinline__ void split2(float x, float y, uint32_t& h, uint32_t& l) {
    __nv_bfloat162 hb = __floats2bfloat162_rn(x, y);
    float hx = __bfloat162float(hb.x), hy = __bfloat162float(hb.y);
    __nv_bfloat162 lb = __floats2bfloat162_rn(x - hx, y - hy);
    h = *(uint32_t*)&hb;
    l = *(uint32_t*)&lb;
}

// ---------------- fp32 -> bf16 hi/lo split (elementwise, float4) ----------------
__global__ __launch_bounds__(1024)
void convA_k(const float* __restrict__ A, __nv_bfloat16* __restrict__ hi,
             __nv_bfloat16* __restrict__ lo)
{
    size_t i = (size_t)blockIdx.x * blockDim.x + threadIdx.x;   // one float4 each
    float4 v = ((const float4*)A)[i];
    union { __nv_bfloat16 b[4]; uint2 u; } ph, pl;
    #pragma unroll
    for (int j = 0; j < 4; j++) {
        float x = (&v.x)[j];
        __nv_bfloat16 h = __float2bfloat16(x);
        ph.b[j] = h;
        pl.b[j] = __float2bfloat16(x - __bfloat162float(h));
    }
    ((uint2*)hi)[i] = ph.u;
    ((uint2*)lo)[i] = pl.u;
}

// ---------------- W [K,N] fp32 -> W^T [N,K] bf16 hi/lo ----------------
__global__ __launch_bounds__(1024)
void convW_k(const float* __restrict__ W, __nv_bfloat16* __restrict__ hi,
             __nv_bfloat16* __restrict__ lo)
{
    __shared__ float t[32][33];
    const int k0 = blockIdx.y * 32, n0 = blockIdx.x * 32;
    t[threadIdx.y][threadIdx.x] = W[(size_t)(k0 + threadIdx.y) * DD + n0 + threadIdx.x];
    __syncthreads();
    float v = t[threadIdx.x][threadIdx.y];   // = W[k0+tx][n0+ty]
    size_t o = (size_t)(n0 + threadIdx.y) * DD + k0 + threadIdx.x;
    __nv_bfloat16 h = __float2bfloat16(v);
    hi[o] = h;
    lo[o] = __float2bfloat16(v - __bfloat162float(h));
}

// ---------------- V fp32 [bh][s][d] -> V^T bf16 hi/lo [bh][d][s] ----------------
__global__ __launch_bounds__(1024)
void convVT_k(const float* __restrict__ vh, __nv_bfloat16* __restrict__ vth,
              __nv_bfloat16* __restrict__ vtl)
{
    __shared__ float t[32][33];
    const int bh = blockIdx.z;
    const int s0 = blockIdx.x * 32, d0 = blockIdx.y * 32;
    t[threadIdx.y][threadIdx.x] =
        vh[((size_t)bh * SS + s0 + threadIdx.y) * HD + d0 + threadIdx.x];
    __syncthreads();
    float v = t[threadIdx.x][threadIdx.y];   // = vh[s0+tx][d0+ty]
    size_t o = ((size_t)bh * HD + d0 + threadIdx.y) * SS + s0 + threadIdx.x;
    __nv_bfloat16 h = __float2bfloat16(v);
    vth[o] = h;
    vtl[o] = __float2bfloat16(v - __bfloat162float(h));
}

// ---------------- mma.sync GEMM: D = Ahi@Bhi + Ahi@Blo + Alo@Bhi ----------------
// cp.async double-buffered. Dynamic smem: 2 stages x 4 tiles x 8KB = 64KB.
// MODE 0: bf16 hi/lo out to head layout, scaled. MODE 1: fp32 [M,N] + residual.
// MODE 2: fp32 head layout.
template<int MODE>
__global__ __launch_bounds__(256)
void gemm_mma(const __nv_bfloat16* __restrict__ Ah, const __nv_bfloat16* __restrict__ Al,
              const __nv_bfloat16* __restrict__ Bh, const __nv_bfloat16* __restrict__ Bl,
              const float* __restrict__ bias, const float* __restrict__ res,
              float* __restrict__ outf, __nv_bfloat16* __restrict__ outh,
              __nv_bfloat16* __restrict__ outl, float scale)
{
    extern __shared__ __align__(16) char dsm[];
    const uint32_t sbase = smem_u32(dsm);

    const int tid = threadIdx.x, lane = tid & 31, wid = tid >> 5;
    const int wm = (wid & 1) * 64, wn = (wid >> 1) * 32;
    const int m0 = blockIdx.y * 128, n0 = blockIdx.x * 128;

    // staging indexing: thread -> (row, two 16B chunks), swizzled
    const int strow = tid >> 1;
    const int stc0  = (tid & 1) * 2;
    const int stsw  = (strow >> 1) & 3;
    const uint32_t so0 = (uint32_t)(strow * 4 + (stc0 ^ stsw)) * 16;
    const uint32_t so1 = (uint32_t)(strow * 4 + ((stc0 + 1) ^ stsw)) * 16;
    const __nv_bfloat16* pAh = Ah + (size_t)(m0 + strow) * DD + stc0 * 8;
    const __nv_bfloat16* pAl = Al + (size_t)(m0 + strow) * DD + stc0 * 8;
    const __nv_bfloat16* pBh = Bh + (size_t)(n0 + strow) * DD + stc0 * 8;
    const __nv_bfloat16* pBl = Bl + (size_t)(n0 + strow) * DD + stc0 * 8;

    // ldmatrix addressing (within 8KB tile, row stride 64B)
    const int la15 = lane & 15;
    const uint32_t Aoff = (uint32_t)(wm + la15) * 64;
    const int swA = (la15 >> 1) & 3;
    const uint32_t cA0 = (uint32_t)(((lane >> 4)     ) ^ swA) * 16;
    const uint32_t cA1 = (uint32_t)((2 + (lane >> 4)) ^ swA) * 16;
    const int la7 = lane & 7;
    const uint32_t Boff = (uint32_t)(wn + la7 + ((lane >> 4) << 3)) * 64;
    const int swB = (la7 >> 1) & 3;
    const uint32_t cB0 = (uint32_t)((((lane >> 3) & 1)    ) ^ swB) * 16;
    const uint32_t cB1 = (uint32_t)((2 + ((lane >> 3) & 1)) ^ swB) * 16;

    float acc[4][4][4];
    #pragma unroll
    for (int mi = 0; mi < 4; mi++)
        #pragma unroll
        for (int ni = 0; ni < 4; ni++)
            #pragma unroll
            for (int r = 0; r < 4; r++) acc[mi][ni][r] = 0.f;

    // prologue: stage chunk 0 into stage 0
    {
        const uint32_t stb = sbase;
        cp16(stb +         so0, pAh);     cp16(stb +         so1, pAh + 8);
        cp16(stb + 8192  + so0, pAl);     cp16(stb + 8192  + so1, pAl + 8);
        cp16(stb + 16384 + so0, pBh);     cp16(stb + 16384 + so1, pBh + 8);
        cp16(stb + 24576 + so0, pBl);     cp16(stb + 24576 + so1, pBl + 8);
        CP_COMMIT();
    }

    for (int kc = 0; kc < 32; kc++) {
        CP_WAIT0();
        __syncthreads();
        if (kc < 31) {
            const int k0 = (kc + 1) * 32;
            const uint32_t stb = sbase + ((kc + 1) & 1) * 32768;
            cp16(stb +         so0, pAh + k0);  cp16(stb +         so1, pAh + k0 + 8);
            cp16(stb + 8192  + so0, pAl + k0);  cp16(stb + 8192  + so1, pAl + k0 + 8);
            cp16(stb + 16384 + so0, pBh + k0);  cp16(stb + 16384 + so1, pBh + k0 + 8);
            cp16(stb + 24576 + so0, pBl + k0);  cp16(stb + 24576 + so1, pBl + k0 + 8);
            CP_COMMIT();
        }
        const uint32_t aAh = sbase + (kc & 1) * 32768;
        const uint32_t aAl = aAh + 8192;
        const uint32_t aBh = aAh + 16384;
        const uint32_t aBl = aAh + 24576;

        #pragma unroll
        for (int ks = 0; ks < 2; ks++) {
            const uint32_t cA = ks ? cA1 : cA0;
            const uint32_t cB = ks ? cB1 : cB0;
            uint32_t a[4][4], a2[4][4], b[2][4], b2[2][4];
            #pragma unroll
            for (int mi = 0; mi < 4; mi++) ldsm4(a[mi], aAh + Aoff + mi * 1024 + cA);
            #pragma unroll
            for (int nt = 0; nt < 2; nt++) ldsm4(b[nt], aBh + Boff + nt * 1024 + cB);
            #pragma unroll
            for (int mi = 0; mi < 4; mi++)
                #pragma unroll
                for (int ni = 0; ni < 4; ni++)
                    mma16816(acc[mi][ni], a[mi], &b[ni >> 1][(ni & 1) * 2]);   // hi*hi
            #pragma unroll
            for (int nt = 0; nt < 2; nt++) ldsm4(b2[nt], aBl + Boff + nt * 1024 + cB);
            #pragma unroll
            for (int mi = 0; mi < 4; mi++)
                #pragma unroll
                for (int ni = 0; ni < 4; ni++)
                    mma16816(acc[mi][ni], a[mi], &b2[ni >> 1][(ni & 1) * 2]);  // hi*lo
            #pragma unroll
            for (int mi = 0; mi < 4; mi++) ldsm4(a2[mi], aAl + Aoff + mi * 1024 + cA);
            #pragma unroll
            for (int mi = 0; mi < 4; mi++)
                #pragma unroll
                for (int ni = 0; ni < 4; ni++)
                    mma16816(acc[mi][ni], a2[mi], &b[ni >> 1][(ni & 1) * 2]);  // lo*hi
        }
    }

    // ---- epilogue ----
    const int gid = lane >> 2, tig = (lane & 3) * 2;
    #pragma unroll
    for (int mi = 0; mi < 4; mi++) {
        #pragma unroll
        for (int rr = 0; rr < 2; rr++) {
            const int m = m0 + wm + mi * 16 + gid + rr * 8;
            #pragma unroll
            for (int ni = 0; ni < 4; ni++) {
                const int col = n0 + wn + ni * 8 + tig;
                const float c0 = acc[mi][ni][rr * 2], c1 = acc[mi][ni][rr * 2 + 1];
                const float2 bb = *(const float2*)(bias + col);
                if (MODE == 0) {
                    const int b_ = m >> 11, s = m & (SS - 1);
                    const int h = col >> 6, d = col & 63;
                    const float v0 = (c0 + bb.x) * scale;
                    const float v1 = (c1 + bb.y) * scale;
                    uint32_t hh, ll;
                    split2(v0, v1, hh, ll);
                    const size_t base = (((size_t)(b_ * HH + h)) * SS + s) * HD + d;
                    *(uint32_t*)(outh + base) = hh;
                    *(uint32_t*)(outl + base) = ll;
                } else if (MODE == 2) {
                    const int b_ = m >> 11, s = m & (SS - 1);
                    const int h = col >> 6, d = col & 63;
                    float* op = outf + (((size_t)(b_ * HH + h)) * SS + s) * HD + d;
                    float2 o; o.x = c0 + bb.x; o.y = c1 + bb.y;
                    *(float2*)op = o;
                } else {
                    const size_t idx = (size_t)m * DD + col;
                    const float2 rv = *(const float2*)(res + idx);
                    float2 o; o.x = c0 + bb.x + rv.x; o.y = c1 + bb.y + rv.y;
                    *(float2*)(outf + idx) = o;
                }
            }
        }
    }
}

// ---------------- suffix sums of V per (b,h): sfx[q] = sum_{k>q} v[k] ----------------
__global__ void sfxA_k(const float* __restrict__ vh, float* __restrict__ sfx,
                       float* __restrict__ ctot)
{
    const int bh = blockIdx.y, c = blockIdx.x, d = threadIdx.x;
    const size_t base = (size_t)bh*SS*HD + d;
    float acc = 0.f;
    for (int s = c*64 + 63; s >= c*64; s--) {
        sfx[base + (size_t)s*HD] = acc;
        acc += vh[base + (size_t)s*HD];
    }
    ctot[((size_t)bh*32 + c)*HD + d] = acc;
}

__global__ void sfxB_k(const float* __restrict__ ctot, float* __restrict__ csfx)
{
    const int bh = blockIdx.x, d = threadIdx.x;
    float acc = 0.f;
    for (int c = 31; c >= 0; c--) {
        csfx[((size_t)bh*32 + c)*HD + d] = acc;
        acc += ctot[((size_t)bh*32 + c)*HD + d];
    }
}

__global__ void sfxC_k(const float* __restrict__ csfx, float* __restrict__ sfx)
{
    const int bh = blockIdx.y, c = blockIdx.x, d = threadIdx.x;
    const float add = csfx[((size_t)bh*32 + c)*HD + d];
    const size_t base = (size_t)bh*SS*HD + d;
    for (int s = c*64; s < c*64 + 64; s++)
        sfx[base + (size_t)s*HD] += add;
}

// ---------------- flash attention with mma.sync, cp.async double-buffered KV ------
// CTA: 64 queries x one (b,h). 128 threads, 4 warps x m16.
// Dynamic smem: Q hi/lo 2x8KB + 2 stages x (Kh,Kl,Vh,Vl) x 8KB = 80KB.
__global__ __launch_bounds__(128)
void attn_mma(const __nv_bfloat16* __restrict__ qhh, const __nv_bfloat16* __restrict__ qhl,
              const __nv_bfloat16* __restrict__ khh, const __nv_bfloat16* __restrict__ khl,
              const __nv_bfloat16* __restrict__ vth, const __nv_bfloat16* __restrict__ vtl,
              const float* __restrict__ sfx, float* __restrict__ ctx)
{
    extern __shared__ __align__(16) char dsma[];
    __nv_bfloat16* sQh = (__nv_bfloat16*)dsma;            // 8KB (64 rows x 128B)
    __nv_bfloat16* sQl = (__nv_bfloat16*)(dsma + 8192);   // 8KB
    const uint32_t qb  = smem_u32(dsma);
    const uint32_t kvb = qb + 16384;                      // KV stages base

    const int tid = threadIdx.x, lane = tid & 31, wid = tid >> 5;
    const int qblk = (int)gridDim.x - 1 - (int)blockIdx.x;   // heavy CTAs first
    const int bh = blockIdx.y;
    const int q0 = qblk * 64;
    const int wm = wid * 16;

    const __nv_bfloat16* Kh0 = khh + (size_t)bh * SS * HD;
    const __nv_bfloat16* Kl0 = khl + (size_t)bh * SS * HD;
    const __nv_bfloat16* Vh0 = vth + (size_t)bh * HD * SS;
    const __nv_bfloat16* Vl0 = vtl + (size_t)bh * HD * SS;

    // prologue: stage 0 <- k-tile 0
    // each tile: 64 rows x 64 bf16 = 8 uint4/row, 512 uint4; 128 threads -> 4 each
    #pragma unroll
    for (int it = 0; it < 4; it++) {
        const int idx = it * 128 + tid;
        const int r = idx >> 3, c = idx & 7;
        const uint32_t sc = (uint32_t)(r * 8 + (c ^ (r & 7))) * 16;
        cp16(kvb +          sc, Kh0 + (size_t)r * HD + c * 8);
        cp16(kvb + 8192   + sc, Kl0 + (size_t)r * HD + c * 8);
        cp16(kvb + 16384  + sc, Vh0 + (size_t)r * SS + c * 8);
        cp16(kvb + 24576  + sc, Vl0 + (size_t)r * SS + c * 8);
    }
    CP_COMMIT();

    // ---- load Q tile (hi/lo), swizzled (regular loads, overlap with cp.async) ----
    {
        const __nv_bfloat16* gh = qhh + ((size_t)bh * SS + q0) * HD;
        const __nv_bfloat16* gl = qhl + ((size_t)bh * SS + q0) * HD;
        #pragma unroll
        for (int it = 0; it < 4; it++) {
            const int idx = it * 128 + tid;
            const int r = idx >> 3, c = idx & 7;
            const int sc = c ^ (r & 7);
            ((uint4*)sQh)[r * 8 + sc] = ((const uint4*)(gh + (size_t)r * HD))[c];
            ((uint4*)sQl)[r * 8 + sc] = ((const uint4*)(gl + (size_t)r * HD))[c];
        }
    }
    __syncthreads();

    // ---- Q fragments (held for whole kernel) ----
    uint32_t qfh[4][4], qfl[4][4];
    {
        const uint32_t aQh = qb, aQl = qb + 8192;
        const int row = wm + (lane & 15);
        const int swr = row & 7;
        const uint32_t rb = (uint32_t)row * 128;
        #pragma unroll
        for (int ks = 0; ks < 4; ks++) {
            const uint32_t c = (uint32_t)((2 * ks + (lane >> 4)) ^ swr) * 16;
            ldsm4(qfh[ks], aQh + rb + c);
            ldsm4(qfl[ks], aQl + rb + c);
        }
    }

    // B-side ldsm addressing (shared by K and V^T tiles; rows of 128B)
    const int brow = (lane & 7) + ((lane >> 4) << 3);   // 0..15
    const int bsw  = brow & 7;
    const int bkb  = (lane >> 3) & 1;

    float O[8][4];
    #pragma unroll
    for (int nb = 0; nb < 8; nb++)
        #pragma unroll
        for (int r = 0; r < 4; r++) O[nb][r] = 0.f;
    float m0 = 0.f, m1 = 0.f, l0 = 0.f, l1 = 0.f;
    const int g = lane >> 2, tig = (lane & 3) * 2;
    const int r0 = q0 + wm + g, r1 = r0 + 8;

    for (int kt = 0; kt <= qblk; kt++) {
        CP_WAIT0();
        __syncthreads();
        if (kt < qblk) {   // stage next k-tile into other buffer
            const int kb2 = (kt + 1) * 64;
            const uint32_t stb = kvb + ((kt + 1) & 1) * 32768;
            #pragma unroll
            for (int it = 0; it < 4; it++) {
                const int idx = it * 128 + tid;
                const int r = idx >> 3, c = idx & 7;
                const uint32_t sc = (uint32_t)(r * 8 + (c ^ (r & 7))) * 16;
                cp16(stb +         sc, Kh0 + (size_t)(kb2 + r) * HD + c * 8);
                cp16(stb + 8192  + sc, Kl0 + (size_t)(kb2 + r) * HD + c * 8);
                cp16(stb + 16384 + sc, Vh0 + (size_t)r * SS + kb2 + c * 8);
                cp16(stb + 24576 + sc, Vl0 + (size_t)r * SS + kb2 + c * 8);
            }
            CP_COMMIT();
        }
        const uint32_t stb = kvb + (kt & 1) * 32768;
        const uint32_t aKh = stb, aKl = stb + 8192, aVh = stb + 16384, aVl = stb + 24576;
        const int kbase = kt * 64;

        // ---- S = Q K^T (3-pass split) ----
        float sacc[8][4];
        #pragma unroll
        for (int nb = 0; nb < 8; nb++)
            #pragma unroll
            for (int r = 0; r < 4; r++) sacc[nb][r] = 0.f;

        #pragma unroll
        for (int ks = 0; ks < 4; ks++) {
            const uint32_t coff = (uint32_t)((2 * ks + bkb) ^ bsw) * 16;
            uint32_t bfr[4][4];
            #pragma unroll
            for (int nt = 0; nt < 4; nt++)
                ldsm4(bfr[nt], aKh + (uint32_t)(nt * 16 + brow) * 128 + coff);
            #pragma unroll
            for (int nb = 0; nb < 8; nb++)
                mma16816(sacc[nb], qfh[ks], &bfr[nb >> 1][(nb & 1) * 2]);   // Qhi*Khi
            #pragma unroll
            for (int nb = 0; nb < 8; nb++)
                mma16816(sacc[nb], qfl[ks], &bfr[nb >> 1][(nb & 1) * 2]);   // Qlo*Khi
            #pragma unroll
            for (int nt = 0; nt < 4; nt++)
                ldsm4(bfr[nt], aKl + (uint32_t)(nt * 16 + brow) * 128 + coff);
            #pragma unroll
            for (int nb = 0; nb < 8; nb++)
                mma16816(sacc[nb], qfh[ks], &bfr[nb >> 1][(nb & 1) * 2]);   // Qhi*Klo
        }

        // ---- causal mask (diagonal tile only) ----
        if (kt == qblk) {
            #pragma unroll
            for (int nb = 0; nb < 8; nb++) {
                const int key = kbase + nb * 8 + tig;
                if (key     > r0) sacc[nb][0] = -1e30f;
                if (key + 1 > r0) sacc[nb][1] = -1e30f;
                if (key     > r1) sacc[nb][2] = -1e30f;
                if (key + 1 > r1) sacc[nb][3] = -1e30f;
            }
        }

        // ---- online softmax ----
        float mx0 = -1e30f, mx1 = -1e30f;
        #pragma unroll
        for (int nb = 0; nb < 8; nb++) {
            mx0 = fmaxf(mx0, fmaxf(sacc[nb][0], sacc[nb][1]));
            mx1 = fmaxf(mx1, fmaxf(sacc[nb][2], sacc[nb][3]));
        }
        mx0 = fmaxf(mx0, __shfl_xor_sync(0xffffffffu, mx0, 1));
        mx0 = fmaxf(mx0, __shfl_xor_sync(0xffffffffu, mx0, 2));
        mx1 = fmaxf(mx1, __shfl_xor_sync(0xffffffffu, mx1, 1));
        mx1 = fmaxf(mx1, __shfl_xor_sync(0xffffffffu, mx1, 2));
        const float mn0 = fmaxf(m0, mx0), mn1 = fmaxf(m1, mx1);
        const float cf0 = __expf(m0 - mn0), cf1 = __expf(m1 - mn1);
        m0 = mn0; m1 = mn1;
        l0 *= cf0; l1 *= cf1;
        #pragma unroll
        for (int nb = 0; nb < 8; nb++) {
            O[nb][0] *= cf0; O[nb][1] *= cf0;
            O[nb][2] *= cf1; O[nb][3] *= cf1;
        }
        float ps0 = 0.f, ps1 = 0.f;
        #pragma unroll
        for (int nb = 0; nb < 8; nb++) {
            const float p0 = __expf(sacc[nb][0] - m0);
            const float p1 = __expf(sacc[nb][1] - m0);
            const float p2 = __expf(sacc[nb][2] - m1);
            const float p3 = __expf(sacc[nb][3] - m1);
            sacc[nb][0] = p0; sacc[nb][1] = p1; sacc[nb][2] = p2; sacc[nb][3] = p3;
            ps0 += p0 + p1; ps1 += p2 + p3;
        }
        ps0 += __shfl_xor_sync(0xffffffffu, ps0, 1);
        ps0 += __shfl_xor_sync(0xffffffffu, ps0, 2);
        ps1 += __shfl_xor_sync(0xffffffffu, ps1, 1);
        ps1 += __shfl_xor_sync(0xffffffffu, ps1, 2);
        l0 += ps0; l1 += ps1;

        // ---- O += P V (3-pass split; P frags straight from registers) ----
        #pragma unroll
        for (int ks = 0; ks < 4; ks++) {
            uint32_t pah[4], pal[4];
            split2(sacc[2*ks  ][0], sacc[2*ks  ][1], pah[0], pal[0]);
            split2(sacc[2*ks  ][2], sacc[2*ks  ][3], pah[1], pal[1]);
            split2(sacc[2*ks+1][0], sacc[2*ks+1][1], pah[2], pal[2]);
            split2(sacc[2*ks+1][2], sacc[2*ks+1][3], pah[3], pal[3]);
            const uint32_t coff = (uint32_t)((2 * ks + bkb) ^ bsw) * 16;
            uint32_t bfr[4][4];
            #pragma unroll
            for (int nt = 0; nt < 4; nt++)
                ldsm4(bfr[nt], aVh + (uint32_t)(nt * 16 + brow) * 128 + coff);
            #pragma unroll
            for (int nb = 0; nb < 8; nb++)
                mma16816(O[nb], pah, &bfr[nb >> 1][(nb & 1) * 2]);   // Phi*Vhi
            #pragma unroll
            for (int nb = 0; nb < 8; nb++)
                mma16816(O[nb], pal, &bfr[nb >> 1][(nb & 1) * 2]);   // Plo*Vhi
            #pragma unroll
            for (int nt = 0; nt < 4; nt++)
                ldsm4(bfr[nt], aVl + (uint32_t)(nt * 16 + brow) * 128 + coff);
            #pragma unroll
            for (int nb = 0; nb < 8; nb++)
                mma16816(O[nb], pah, &bfr[nb >> 1][(nb & 1) * 2]);   // Phi*Vlo
        }
    }

    // ---- finalize: fold masked (post-causal) contribution, normalize, write ----
    const float em0 = __expf(-m0), em1 = __expf(-m1);
    const float lt0 = l0 + (float)(SS - 1 - r0) * em0;
    const float lt1 = l1 + (float)(SS - 1 - r1) * em1;
    const float inv0 = 1.f / lt0, inv1 = 1.f / lt1;
    const int b_ = bh >> 4, h = bh & 15;
    const float* sp0 = sfx + ((size_t)bh * SS + r0) * HD;
    const float* sp1 = sfx + ((size_t)bh * SS + r1) * HD;
    float* o0 = ctx + ((size_t)(b_ * SS + r0)) * DD + h * HD;
    float* o1 = ctx + ((size_t)(b_ * SS + r1)) * DD + h * HD;
    #pragma unroll
    for (int nb = 0; nb < 8; nb++) {
        const int d = nb * 8 + tig;
        const float2 sv0 = *(const float2*)(sp0 + d);
        const float2 sv1 = *(const float2*)(sp1 + d);
        float2 w0, w1;
        w0.x = (O[nb][0] + em0 * sv0.x) * inv0;
        w0.y = (O[nb][1] + em0 * sv0.y) * inv0;
        w1.x = (O[nb][2] + em1 * sv1.x) * inv1;
        w1.y = (O[nb][3] + em1 * sv1.y) * inv1;
        *(float2*)(o0 + d) = w0;
        *(float2*)(o1 + d) = w1;
    }
}

// ---------------- LayerNorm (in place on d_out) ----------------
__global__ __launch_bounds__(256)
void ln_k(float* __restrict__ out, const float* __restrict__ gamma,
          const float* __restrict__ beta)
{
    const int row = blockIdx.x;
    float* p = out + (size_t)row*DD;
    const int t = threadIdx.x;
    float4 v = ((const float4*)p)[t];
    float sum = v.x + v.y + v.z + v.w;
    float sq  = v.x*v.x + v.y*v.y + v.z*v.z + v.w*v.w;
    #pragma unroll
    for (int o = 16; o > 0; o >>= 1) {
        sum += __shfl_xor_sync(0xffffffffu, sum, o);
        sq  += __shfl_xor_sync(0xffffffffu, sq,  o);
    }
    __shared__ float s1[8], s2[8];
    if ((t & 31) == 0) { s1[t >> 5] = sum; s2[t >> 5] = sq; }
    __syncthreads();
    __shared__ float smu, srstd;
    if (t < 32) {
        float a = (t < 8) ? s1[t] : 0.f;
        float b = (t < 8) ? s2[t] : 0.f;
        #pragma unroll
        for (int o = 4; o > 0; o >>= 1) {
            a += __shfl_xor_sync(0xffffffffu, a, o);
            b += __shfl_xor_sync(0xffffffffu, b, o);
        }
        if (t == 0) {
            float mu  = a * (1.f/DD);
            float var = b * (1.f/DD) - mu*mu;
            smu = mu;
            srstd = rsqrtf(var + 1e-5f);
        }
    }
    __syncthreads();
    const float mu = smu, rs = srstd;
    float4 gm = ((const float4*)gamma)[t];
    float4 be = ((const float4*)beta)[t];
    v.x = (v.x - mu)*rs*gm.x + be.x;
    v.y = (v.y - mu)*rs*gm.y + be.y;
    v.z = (v.z - mu)*rs*gm.z + be.z;
    v.w = (v.w - mu)*rs*gm.w + be.w;
    ((float4*)p)[t] = v;
}

// ---------------- launch ----------------
extern "C" void kernel_launch(void* const* d_in, const int* in_sizes, int n_in,
                              void* d_out, int out_size)
{
    const float* q     = (const float*)d_in[0];
    const float* k     = (const float*)d_in[1];
    const float* v     = (const float*)d_in[2];
    const float* Wq    = (const float*)d_in[3];
    const float* bq    = (const float*)d_in[4];
    const float* Wk    = (const float*)d_in[5];
    const float* bk    = (const float*)d_in[6];
    const float* Wv    = (const float*)d_in[7];
    const float* bv    = (const float*)d_in[8];
    const float* Wp    = (const float*)d_in[9];
    const float* bp    = (const float*)d_in[10];
    const float* gamma = (const float*)d_in[11];
    const float* beta  = (const float*)d_in[12];
    float* out = (float*)d_out;

    float *vh, *sfx, *ctx, *ctot, *csfx;
    __nv_bfloat16 *qhh, *qhl, *khh, *khl, *vth, *vtl, *wth, *wtl, *ah, *al;
    cudaGetSymbolAddress((void**)&qhh, g_qhh);
    cudaGetSymbolAddress((void**)&qhl, g_qhl);
    cudaGetSymbolAddress((void**)&khh, g_khh);
    cudaGetSymbolAddress((void**)&khl, g_khl);
    cudaGetSymbolAddress((void**)&vh,  g_vh);
    cudaGetSymbolAddress((void**)&vth, g_vth);
    cudaGetSymbolAddress((void**)&vtl, g_vtl);
    cudaGetSymbolAddress((void**)&sfx, g_sfx);
    cudaGetSymbolAddress((void**)&ctx, g_ctx);
    cudaGetSymbolAddress((void**)&ctot, g_ctot);
    cudaGetSymbolAddress((void**)&csfx, g_csfx);
    cudaGetSymbolAddress((void**)&wth, g_wth);
    cudaGetSymbolAddress((void**)&wtl, g_wtl);
    cudaGetSymbolAddress((void**)&ah,  g_ah);
    cudaGetSymbolAddress((void**)&al,  g_al);

    cudaFuncSetAttribute(reinterpret_cast<const void*>(gemm_mma<0>),
                         cudaFuncAttributeMaxDynamicSharedMemorySize, 65536);
    cudaFuncSetAttribute(reinterpret_cast<const void*>(gemm_mma<1>),
                         cudaFuncAttributeMaxDynamicSharedMemorySize, 65536);
    cudaFuncSetAttribute(reinterpret_cast<const void*>(gemm_mma<2>),
                         cudaFuncAttributeMaxDynamicSharedMemorySize, 65536);
    cudaFuncSetAttribute(reinterpret_cast<const void*>(attn_mma),
                         cudaFuncAttributeMaxDynamicSharedMemorySize, 81920);

    // weights: transpose + hi/lo split
    dim3 cwg(32, 32), cwb(32, 32);
    convW_k<<<cwg, cwb>>>(Wq, wth + 0*(size_t)WSZ, wtl + 0*(size_t)WSZ);
    convW_k<<<cwg, cwb>>>(Wk, wth + 1*(size_t)WSZ, wtl + 1*(size_t)WSZ);
    convW_k<<<cwg, cwb>>>(Wv, wth + 2*(size_t)WSZ, wtl + 2*(size_t)WSZ);
    convW_k<<<cwg, cwb>>>(Wp, wth + 3*(size_t)WSZ, wtl + 3*(size_t)WSZ);

    dim3 gg(DD/128, MM/128);   // (8, 64)

    // Q: bf16 hi/lo, pre-scaled by 1/sqrt(HD)
    convA_k<<<2048, 1024>>>(q, ah, al);
    gemm_mma<0><<<gg, 256, 65536>>>(ah, al, wth + 0*(size_t)WSZ, wtl + 0*(size_t)WSZ, bq,
                                    nullptr, nullptr, qhh, qhl, 0.125f);
    // K: bf16 hi/lo
    convA_k<<<2048, 1024>>>(k, ah, al);
    gemm_mma<0><<<gg, 256, 65536>>>(ah, al, wth + 1*(size_t)WSZ, wtl + 1*(size_t)WSZ, bk,
                                    nullptr, nullptr, khh, khl, 1.0f);
    // V: fp32 head layout (for suffix sums) + transposed bf16 hi/lo
    convA_k<<<2048, 1024>>>(v, ah, al);
    gemm_mma<2><<<gg, 256, 65536>>>(ah, al, wth + 2*(size_t)WSZ, wtl + 2*(size_t)WSZ, bv,
                                    nullptr, vh, nullptr, nullptr, 1.0f);

    dim3 gs(32, NBH);
    sfxA_k<<<gs, 64>>>(vh, sfx, ctot);
    sfxB_k<<<NBH, 64>>>(ctot, csfx);
    sfxC_k<<<gs, 64>>>(csfx, sfx);
    convVT_k<<<dim3(SS/32, HD/32, NBH), dim3(32, 32)>>>(vh, vth, vtl);

    attn_mma<<<dim3(SS/64, NBH), 128, 81920>>>(qhh, qhl, khh, khl, vth, vtl, sfx, ctx);

    convA_k<<<2048, 1024>>>(ctx, ah, al);
    gemm_mma<1><<<gg, 256, 65536>>>(ah, al, wth + 3*(size_t)WSZ, wtl + 3*(size_t)WSZ, bp,
                                    q, out, nullptr, nullptr, 1.0f);
    ln_k<<<MM, 256>>>(out, gamma, beta);
}

// round 13
// speedup vs baseline: 3.3999x; 1.0724x over previous
#include <cuda_runtime.h>
#include <cuda_bf16.h>
#include <cstdint>

#define BB 4
#define SS 2048
#define DD 1024
#define HH 16
#define HD 64
#define MM (BB*SS)   // 8192 rows
#define WSZ (1024*1024)
#define NBH (BB*HH)  // 64
#define BQ 128       // attention q-tile

// ---------------- scratch (no allocations allowed) ----------------
__device__ __nv_bfloat16 g_qhh[(size_t)NBH*SS*HD];  // Q heads hi (pre-scaled by 1/8)
__device__ __nv_bfloat16 g_qhl[(size_t)NBH*SS*HD];  // Q heads lo
__device__ __nv_bfloat16 g_khh[(size_t)NBH*SS*HD];
__device__ __nv_bfloat16 g_khl[(size_t)NBH*SS*HD];
__device__ float g_vh [(size_t)NBH*SS*HD];          // V heads fp32 [bh][s][d]
__device__ __nv_bfloat16 g_vth[(size_t)NBH*HD*SS];  // V^T hi [bh][d][s]
__device__ __nv_bfloat16 g_vtl[(size_t)NBH*HD*SS];  // V^T lo
__device__ float g_sfx[(size_t)NBH*SS*HD];          // suffix sums of V per head
__device__ float g_ctot[(size_t)NBH*32*HD];
__device__ float g_csfx[(size_t)NBH*32*HD];
__device__ __nv_bfloat16 g_wth[(size_t)4*WSZ];      // W^T hi, [N,K] per weight
__device__ __nv_bfloat16 g_wtl[(size_t)4*WSZ];      // W^T lo
__device__ __nv_bfloat16 g_ahq[(size_t)MM*DD];      // activations hi/lo per input
__device__ __nv_bfloat16 g_alq[(size_t)MM*DD];
__device__ __nv_bfloat16 g_ahk[(size_t)MM*DD];
__device__ __nv_bfloat16 g_alk[(size_t)MM*DD];
__device__ __nv_bfloat16 g_ahv[(size_t)MM*DD];
__device__ __nv_bfloat16 g_alv[(size_t)MM*DD];
__device__ __nv_bfloat16 g_cth[(size_t)MM*DD];      // attention out hi/lo [B,S,D]
__device__ __nv_bfloat16 g_ctl[(size_t)MM*DD];

// ---------------- helpers ----------------
__device__ __forceinline__ uint32_t smem_u32(const void* p) {
    uint32_t a;
    asm("{ .reg .u64 t; cvta.to.shared.u64 t, %1; cvt.u32.u64 %0, t; }" : "=r"(a) : "l"(p));
    return a;
}
__device__ __forceinline__ void ldsm4(uint32_t* r, uint32_t addr) {
    asm volatile("ldmatrix.sync.aligned.m8n8.x4.shared.b16 {%0,%1,%2,%3}, [%4];"
        : "=r"(r[0]), "=r"(r[1]), "=r"(r[2]), "=r"(r[3]) : "r"(addr));
}
__device__ __forceinline__ void mma16816(float* c, const uint32_t* a, const uint32_t* b) {
    asm volatile("mma.sync.aligned.m16n8k16.row.col.f32.bf16.bf16.f32 "
        "{%0,%1,%2,%3}, {%4,%5,%6,%7}, {%8,%9}, {%0,%1,%2,%3};"
        : "+f"(c[0]), "+f"(c[1]), "+f"(c[2]), "+f"(c[3])
        : "r"(a[0]), "r"(a[1]), "r"(a[2]), "r"(a[3]), "r"(b[0]), "r"(b[1]));
}
__device__ __forceinline__ void cp16(uint32_t dst, const void* src) {
    asm volatile("cp.async.cg.shared.global [%0], [%1], 16;" :: "r"(dst), "l"(src));
}
#define CP_COMMIT() asm volatile("cp.async.commit_group;" ::: "memory")
#define CP_WAIT0()  asm volatile("cp.async.wait_group 0;" ::: "memory")

// split a pair of floats into packed bf16 hi and lo (x in low half)
__device__ __forceinline__ void split2(float x, float y, uint32_t& h, uint32_t& l) {
    __nv_bfloat162 hb = __floats2bfloat162_rn(x, y);
    float hx = __bfloat162float(hb.x), hy = __bfloat162float(hb.y);
    __nv_bfloat162 lb = __floats2bfloat162_rn(x - hx, y - hy);
    h = *(uint32_t*)&hb;
    l = *(uint32_t*)&lb;
}

// ---------------- fp32 -> bf16 hi/lo split, 3 tensors in one launch ----------------
__global__ __launch_bounds__(1024)
void convA3_k(const float* __restrict__ q, const float* __restrict__ k,
              const float* __restrict__ v,
              __nv_bfloat16* __restrict__ hq, __nv_bfloat16* __restrict__ lq,
              __nv_bfloat16* __restrict__ hk, __nv_bfloat16* __restrict__ lk,
              __nv_bfloat16* __restrict__ hv, __nv_bfloat16* __restrict__ lv)
{
    const int z = blockIdx.z;
    const float* A = (z == 0) ? q : (z == 1) ? k : v;
    __nv_bfloat16* hi = (z == 0) ? hq : (z == 1) ? hk : hv;
    __nv_bfloat16* lo = (z == 0) ? lq : (z == 1) ? lk : lv;
    size_t i = (size_t)blockIdx.x * blockDim.x + threadIdx.x;   // one float4 each
    float4 vv = ((const float4*)A)[i];
    union { __nv_bfloat16 b[4]; uint2 u; } ph, pl;
    #pragma unroll
    for (int j = 0; j < 4; j++) {
        float x = (&vv.x)[j];
        __nv_bfloat16 h = __float2bfloat16(x);
        ph.b[j] = h;
        pl.b[j] = __float2bfloat16(x - __bfloat162float(h));
    }
    ((uint2*)hi)[i] = ph.u;
    ((uint2*)lo)[i] = pl.u;
}

// ---------------- 4x W [K,N] fp32 -> W^T [N,K] bf16 hi/lo (one launch) -------------
__global__ __launch_bounds__(1024)
void convW4_k(const float* __restrict__ Wq, const float* __restrict__ Wk,
              const float* __restrict__ Wv, const float* __restrict__ Wp,
              __nv_bfloat16* __restrict__ hi4, __nv_bfloat16* __restrict__ lo4)
{
    const int z = blockIdx.z;
    const float* W = (z == 0) ? Wq : (z == 1) ? Wk : (z == 2) ? Wv : Wp;
    __nv_bfloat16* hi = hi4 + (size_t)z * WSZ;
    __nv_bfloat16* lo = lo4 + (size_t)z * WSZ;
    __shared__ float t[32][33];
    const int k0 = blockIdx.y * 32, n0 = blockIdx.x * 32;
    t[threadIdx.y][threadIdx.x] = W[(size_t)(k0 + threadIdx.y) * DD + n0 + threadIdx.x];
    __syncthreads();
    float v = t[threadIdx.x][threadIdx.y];   // = W[k0+tx][n0+ty]
    size_t o = (size_t)(n0 + threadIdx.y) * DD + k0 + threadIdx.x;
    __nv_bfloat16 h = __float2bfloat16(v);
    hi[o] = h;
    lo[o] = __float2bfloat16(v - __bfloat162float(h));
}

// ---------------- V fp32 [bh][s][d] -> V^T bf16 hi/lo [bh][d][s] ----------------
__global__ __launch_bounds__(1024)
void convVT_k(const float* __restrict__ vh, __nv_bfloat16* __restrict__ vth,
              __nv_bfloat16* __restrict__ vtl)
{
    __shared__ float t[32][33];
    const int bh = blockIdx.z;
    const int s0 = blockIdx.x * 32, d0 = blockIdx.y * 32;
    t[threadIdx.y][threadIdx.x] =
        vh[((size_t)bh * SS + s0 + threadIdx.y) * HD + d0 + threadIdx.x];
    __syncthreads();
    float v = t[threadIdx.x][threadIdx.y];   // = vh[s0+tx][d0+ty]
    size_t o = ((size_t)bh * HD + d0 + threadIdx.y) * SS + s0 + threadIdx.x;
    __nv_bfloat16 h = __float2bfloat16(v);
    vth[o] = h;
    vtl[o] = __float2bfloat16(v - __bfloat162float(h));
}

// ================= shared GEMM core (cp.async double-buffered) =================
// computes acc[4][4][4] for CTA tile (m0,n0); smem: 2 stages x 32KB
struct GemmCore {
    uint32_t so0, so1;
    const __nv_bfloat16 *pAh, *pAl, *pBh, *pBl;
    uint32_t Aoff, cA0, cA1, Boff, cB0, cB1;
};

__device__ __forceinline__ void gemm_core_run(
    const __nv_bfloat16* Ah, const __nv_bfloat16* Al,
    const __nv_bfloat16* Bh, const __nv_bfloat16* Bl,
    int m0, int n0, uint32_t sbase, float acc[4][4][4])
{
    const int tid = threadIdx.x, lane = tid & 31, wid = tid >> 5;
    const int wm = (wid & 1) * 64, wn = (wid >> 1) * 32;

    const int strow = tid >> 1;
    const int stc0  = (tid & 1) * 2;
    const int stsw  = (strow >> 1) & 3;
    const uint32_t so0 = (uint32_t)(strow * 4 + (stc0 ^ stsw)) * 16;
    const uint32_t so1 = (uint32_t)(strow * 4 + ((stc0 + 1) ^ stsw)) * 16;
    const __nv_bfloat16* pAh = Ah + (size_t)(m0 + strow) * DD + stc0 * 8;
    const __nv_bfloat16* pAl = Al + (size_t)(m0 + strow) * DD + stc0 * 8;
    const __nv_bfloat16* pBh = Bh + (size_t)(n0 + strow) * DD + stc0 * 8;
    const __nv_bfloat16* pBl = Bl + (size_t)(n0 + strow) * DD + stc0 * 8;

    const int la15 = lane & 15;
    const uint32_t Aoff = (uint32_t)(wm + la15) * 64;
    const int swA = (la15 >> 1) & 3;
    const uint32_t cA0 = (uint32_t)(((lane >> 4)     ) ^ swA) * 16;
    const uint32_t cA1 = (uint32_t)((2 + (lane >> 4)) ^ swA) * 16;
    const int la7 = lane & 7;
    const uint32_t Boff = (uint32_t)(wn + la7 + ((lane >> 4) << 3)) * 64;
    const int swB = (la7 >> 1) & 3;
    const uint32_t cB0 = (uint32_t)((((lane >> 3) & 1)    ) ^ swB) * 16;
    const uint32_t cB1 = (uint32_t)((2 + ((lane >> 3) & 1)) ^ swB) * 16;

    // prologue
    {
        const uint32_t stb = sbase;
        cp16(stb +         so0, pAh);     cp16(stb +         so1, pAh + 8);
        cp16(stb + 8192  + so0, pAl);     cp16(stb + 8192  + so1, pAl + 8);
        cp16(stb + 16384 + so0, pBh);     cp16(stb + 16384 + so1, pBh + 8);
        cp16(stb + 24576 + so0, pBl);     cp16(stb + 24576 + so1, pBl + 8);
        CP_COMMIT();
    }

    for (int kc = 0; kc < 32; kc++) {
        CP_WAIT0();
        __syncthreads();
        if (kc < 31) {
            const int k0 = (kc + 1) * 32;
            const uint32_t stb = sbase + ((kc + 1) & 1) * 32768;
            cp16(stb +         so0, pAh + k0);  cp16(stb +         so1, pAh + k0 + 8);
            cp16(stb + 8192  + so0, pAl + k0);  cp16(stb + 8192  + so1, pAl + k0 + 8);
            cp16(stb + 16384 + so0, pBh + k0);  cp16(stb + 16384 + so1, pBh + k0 + 8);
            cp16(stb + 24576 + so0, pBl + k0);  cp16(stb + 24576 + so1, pBl + k0 + 8);
            CP_COMMIT();
        }
        const uint32_t aAh = sbase + (kc & 1) * 32768;
        const uint32_t aAl = aAh + 8192;
        const uint32_t aBh = aAh + 16384;
        const uint32_t aBl = aAh + 24576;

        #pragma unroll
        for (int ks = 0; ks < 2; ks++) {
            const uint32_t cA = ks ? cA1 : cA0;
            const uint32_t cB = ks ? cB1 : cB0;
            uint32_t a[4][4], a2[4][4], b[2][4], b2[2][4];
            #pragma unroll
            for (int mi = 0; mi < 4; mi++) ldsm4(a[mi], aAh + Aoff + mi * 1024 + cA);
            #pragma unroll
            for (int nt = 0; nt < 2; nt++) ldsm4(b[nt], aBh + Boff + nt * 1024 + cB);
            #pragma unroll
            for (int mi = 0; mi < 4; mi++)
                #pragma unroll
                for (int ni = 0; ni < 4; ni++)
                    mma16816(acc[mi][ni], a[mi], &b[ni >> 1][(ni & 1) * 2]);   // hi*hi
            #pragma unroll
            for (int nt = 0; nt < 2; nt++) ldsm4(b2[nt], aBl + Boff + nt * 1024 + cB);
            #pragma unroll
            for (int mi = 0; mi < 4; mi++)
                #pragma unroll
                for (int ni = 0; ni < 4; ni++)
                    mma16816(acc[mi][ni], a[mi], &b2[ni >> 1][(ni & 1) * 2]);  // hi*lo
            #pragma unroll
            for (int mi = 0; mi < 4; mi++) ldsm4(a2[mi], aAl + Aoff + mi * 1024 + cA);
            #pragma unroll
            for (int mi = 0; mi < 4; mi++)
                #pragma unroll
                for (int ni = 0; ni < 4; ni++)
                    mma16816(acc[mi][ni], a2[mi], &b[ni >> 1][(ni & 1) * 2]);  // lo*hi
        }
    }
}

// ---------------- merged QKV GEMM (grid.z selects tensor) ----------------
__global__ __launch_bounds__(256)
void gemm_qkv(const __nv_bfloat16* __restrict__ ahq, const __nv_bfloat16* __restrict__ alq,
              const __nv_bfloat16* __restrict__ ahk, const __nv_bfloat16* __restrict__ alk,
              const __nv_bfloat16* __restrict__ ahv, const __nv_bfloat16* __restrict__ alv,
              const __nv_bfloat16* __restrict__ wth, const __nv_bfloat16* __restrict__ wtl,
              const float* __restrict__ bq, const float* __restrict__ bk,
              const float* __restrict__ bv,
              __nv_bfloat16* __restrict__ qhh, __nv_bfloat16* __restrict__ qhl,
              __nv_bfloat16* __restrict__ khh, __nv_bfloat16* __restrict__ khl,
              float* __restrict__ vhf)
{
    extern __shared__ __align__(16) char dsm[];
    const int z = blockIdx.z;
    const __nv_bfloat16* Ah = (z == 0) ? ahq : (z == 1) ? ahk : ahv;
    const __nv_bfloat16* Al = (z == 0) ? alq : (z == 1) ? alk : alv;
    const __nv_bfloat16* Bh = wth + (size_t)z * WSZ;
    const __nv_bfloat16* Bl = wtl + (size_t)z * WSZ;
    const float* bias = (z == 0) ? bq : (z == 1) ? bk : bv;
    const float scale = (z == 0) ? 0.125f : 1.0f;

    const int m0 = blockIdx.y * 128, n0 = blockIdx.x * 128;
    float acc[4][4][4];
    #pragma unroll
    for (int mi = 0; mi < 4; mi++)
        #pragma unroll
        for (int ni = 0; ni < 4; ni++)
            #pragma unroll
            for (int r = 0; r < 4; r++) acc[mi][ni][r] = 0.f;

    gemm_core_run(Ah, Al, Bh, Bl, m0, n0, smem_u32(dsm), acc);

    const int lane = threadIdx.x & 31, wid = threadIdx.x >> 5;
    const int wm = (wid & 1) * 64, wn = (wid >> 1) * 32;
    const int gid = lane >> 2, tig = (lane & 3) * 2;
    #pragma unroll
    for (int mi = 0; mi < 4; mi++) {
        #pragma unroll
        for (int rr = 0; rr < 2; rr++) {
            const int m = m0 + wm + mi * 16 + gid + rr * 8;
            const int b_ = m >> 11, s = m & (SS - 1);
            #pragma unroll
            for (int ni = 0; ni < 4; ni++) {
                const int col = n0 + wn + ni * 8 + tig;
                const float c0 = acc[mi][ni][rr * 2], c1 = acc[mi][ni][rr * 2 + 1];
                const float2 bb = *(const float2*)(bias + col);
                const int h = col >> 6, d = col & 63;
                const size_t base = (((size_t)(b_ * HH + h)) * SS + s) * HD + d;
                if (z == 2) {
                    float2 o; o.x = c0 + bb.x; o.y = c1 + bb.y;
                    *(float2*)(vhf + base) = o;
                } else {
                    const float v0 = (c0 + bb.x) * scale;
                    const float v1 = (c1 + bb.y) * scale;
                    uint32_t hh, ll;
                    split2(v0, v1, hh, ll);
                    __nv_bfloat16* oh = (z == 0) ? qhh : khh;
                    __nv_bfloat16* ol = (z == 0) ? qhl : khl;
                    *(uint32_t*)(oh + base) = hh;
                    *(uint32_t*)(ol + base) = ll;
                }
            }
        }
    }
}

// ---------------- output projection GEMM: fp32 [M,N] + bias + residual ----------
__global__ __launch_bounds__(256)
void gemm_proj(const __nv_bfloat16* __restrict__ Ah, const __nv_bfloat16* __restrict__ Al,
               const __nv_bfloat16* __restrict__ Bh, const __nv_bfloat16* __restrict__ Bl,
               const float* __restrict__ bias, const float* __restrict__ res,
               float* __restrict__ outf)
{
    extern __shared__ __align__(16) char dsm[];
    const int m0 = blockIdx.y * 128, n0 = blockIdx.x * 128;
    float acc[4][4][4];
    #pragma unroll
    for (int mi = 0; mi < 4; mi++)
        #pragma unroll
        for (int ni = 0; ni < 4; ni++)
            #pragma unroll
            for (int r = 0; r < 4; r++) acc[mi][ni][r] = 0.f;

    gemm_core_run(Ah, Al, Bh, Bl, m0, n0, smem_u32(dsm), acc);

    const int lane = threadIdx.x & 31, wid = threadIdx.x >> 5;
    const int wm = (wid & 1) * 64, wn = (wid >> 1) * 32;
    const int gid = lane >> 2, tig = (lane & 3) * 2;
    #pragma unroll
    for (int mi = 0; mi < 4; mi++) {
        #pragma unroll
        for (int rr = 0; rr < 2; rr++) {
            const int m = m0 + wm + mi * 16 + gid + rr * 8;
            #pragma unroll
            for (int ni = 0; ni < 4; ni++) {
                const int col = n0 + wn + ni * 8 + tig;
                const float c0 = acc[mi][ni][rr * 2], c1 = acc[mi][ni][rr * 2 + 1];
                const float2 bb = *(const float2*)(bias + col);
                const size_t idx = (size_t)m * DD + col;
                const float2 rv = *(const float2*)(res + idx);
                float2 o; o.x = c0 + bb.x + rv.x; o.y = c1 + bb.y + rv.y;
                *(float2*)(outf + idx) = o;
            }
        }
    }
}

// ---------------- suffix sums of V per (b,h): sfx[q] = sum_{k>q} v[k] ----------------
__global__ void sfxA_k(const float* __restrict__ vh, float* __restrict__ sfx,
                       float* __restrict__ ctot)
{
    const int bh = blockIdx.y, c = blockIdx.x, d = threadIdx.x;
    const size_t base = (size_t)bh*SS*HD + d;
    float acc = 0.f;
    for (int s = c*64 + 63; s >= c*64; s--) {
        sfx[base + (size_t)s*HD] = acc;
        acc += vh[base + (size_t)s*HD];
    }
    ctot[((size_t)bh*32 + c)*HD + d] = acc;
}

__global__ void sfxB_k(const float* __restrict__ ctot, float* __restrict__ csfx)
{
    const int bh = blockIdx.x, d = threadIdx.x;
    float acc = 0.f;
    for (int c = 31; c >= 0; c--) {
        csfx[((size_t)bh*32 + c)*HD + d] = acc;
        acc += ctot[((size_t)bh*32 + c)*HD + d];
    }
}

__global__ void sfxC_k(const float* __restrict__ csfx, float* __restrict__ sfx)
{
    const int bh = blockIdx.y, c = blockIdx.x, d = threadIdx.x;
    const float add = csfx[((size_t)bh*32 + c)*HD + d];
    const size_t base = (size_t)bh*SS*HD + d;
    for (int s = c*64; s < c*64 + 64; s++)
        sfx[base + (size_t)s*HD] += add;
}

// ---------------- flash attention: 128 queries/CTA, 8 warps, cp.async KV ----------
// Dynamic smem: Q hi/lo 2x16KB + 2 stages x (Kh,Kl,Vh,Vl) x 8KB = 96KB.
// Output: bf16 hi/lo ctx (feeds projection GEMM directly).
__global__ __launch_bounds__(256)
void attn_mma(const __nv_bfloat16* __restrict__ qhh, const __nv_bfloat16* __restrict__ qhl,
              const __nv_bfloat16* __restrict__ khh, const __nv_bfloat16* __restrict__ khl,
              const __nv_bfloat16* __restrict__ vth, const __nv_bfloat16* __restrict__ vtl,
              const float* __restrict__ sfx,
              __nv_bfloat16* __restrict__ cth, __nv_bfloat16* __restrict__ ctl)
{
    extern __shared__ __align__(16) char dsma[];
    __nv_bfloat16* sQh = (__nv_bfloat16*)dsma;             // 16KB (128 rows x 128B)
    __nv_bfloat16* sQl = (__nv_bfloat16*)(dsma + 16384);   // 16KB
    const uint32_t qb  = smem_u32(dsma);
    const uint32_t kvb = qb + 32768;                       // KV stages base

    const int tid = threadIdx.x, lane = tid & 31, wid = tid >> 5;   // wid 0..7
    const int qblk = (int)gridDim.x - 1 - (int)blockIdx.x;          // heavy CTAs first
    const int bh = blockIdx.y;
    const int q0 = qblk * BQ;
    const int wm = wid * 16;
    const int ntiles = 2 * qblk + 2;

    const __nv_bfloat16* Kh0 = khh + (size_t)bh * SS * HD;
    const __nv_bfloat16* Kl0 = khl + (size_t)bh * SS * HD;
    const __nv_bfloat16* Vh0 = vth + (size_t)bh * HD * SS;
    const __nv_bfloat16* Vl0 = vtl + (size_t)bh * HD * SS;

    // prologue: stage 0 <- k-tile 0 (each tile 64x64 bf16 = 512 uint4; 256 thr -> 2 ea)
    #pragma unroll
    for (int it = 0; it < 2; it++) {
        const int idx = it * 256 + tid;
        const int r = idx >> 3, c = idx & 7;
        const uint32_t sc = (uint32_t)(r * 8 + (c ^ (r & 7))) * 16;
        cp16(kvb +          sc, Kh0 + (size_t)r * HD + c * 8);
        cp16(kvb + 8192   + sc, Kl0 + (size_t)r * HD + c * 8);
        cp16(kvb + 16384  + sc, Vh0 + (size_t)r * SS + c * 8);
        cp16(kvb + 24576  + sc, Vl0 + (size_t)r * SS + c * 8);
    }
    CP_COMMIT();

    // ---- load Q tile (hi/lo), swizzled (128 rows x 8 uint4 = 1024 per array) ----
    {
        const __nv_bfloat16* gh = qhh + ((size_t)bh * SS + q0) * HD;
        const __nv_bfloat16* gl = qhl + ((size_t)bh * SS + q0) * HD;
        #pragma unroll
        for (int it = 0; it < 4; it++) {
            const int idx = it * 256 + tid;
            const int r = idx >> 3, c = idx & 7;
            const int sc = c ^ (r & 7);
            ((uint4*)sQh)[r * 8 + sc] = ((const uint4*)(gh + (size_t)r * HD))[c];
            ((uint4*)sQl)[r * 8 + sc] = ((const uint4*)(gl + (size_t)r * HD))[c];
        }
    }
    __syncthreads();

    // ---- Q fragments (held for whole kernel) ----
    uint32_t qfh[4][4], qfl[4][4];
    {
        const uint32_t aQh = qb, aQl = qb + 16384;
        const int row = wm + (lane & 15);
        const int swr = row & 7;
        const uint32_t rb = (uint32_t)row * 128;
        #pragma unroll
        for (int ks = 0; ks < 4; ks++) {
            const uint32_t c = (uint32_t)((2 * ks + (lane >> 4)) ^ swr) * 16;
            ldsm4(qfh[ks], aQh + rb + c);
            ldsm4(qfl[ks], aQl + rb + c);
        }
    }

    // B-side ldsm addressing (shared by K and V^T tiles; rows of 128B)
    const int brow = (lane & 7) + ((lane >> 4) << 3);   // 0..15
    const int bsw  = brow & 7;
    const int bkb  = (lane >> 3) & 1;

    float O[8][4];
    #pragma unroll
    for (int nb = 0; nb < 8; nb++)
        #pragma unroll
        for (int r = 0; r < 4; r++) O[nb][r] = 0.f;
    float m0 = 0.f, m1 = 0.f, l0 = 0.f, l1 = 0.f;
    const int g = lane >> 2, tig = (lane & 3) * 2;
    const int r0 = q0 + wm + g, r1 = r0 + 8;

    for (int kt = 0; kt < ntiles; kt++) {
        CP_WAIT0();
        __syncthreads();
        if (kt < ntiles - 1) {   // stage next k-tile into other buffer
            const int kb2 = (kt + 1) * 64;
            const uint32_t stb = kvb + ((kt + 1) & 1) * 32768;
            #pragma unroll
            for (int it = 0; it < 2; it++) {
                const int idx = it * 256 + tid;
                const int r = idx >> 3, c = idx & 7;
                const uint32_t sc = (uint32_t)(r * 8 + (c ^ (r & 7))) * 16;
                cp16(stb +         sc, Kh0 + (size_t)(kb2 + r) * HD + c * 8);
                cp16(stb + 8192  + sc, Kl0 + (size_t)(kb2 + r) * HD + c * 8);
                cp16(stb + 16384 + sc, Vh0 + (size_t)r * SS + kb2 + c * 8);
                cp16(stb + 24576 + sc, Vl0 + (size_t)r * SS + kb2 + c * 8);
            }
            CP_COMMIT();
        }
        const uint32_t stb = kvb + (kt & 1) * 32768;
        const uint32_t aKh = stb, aKl = stb + 8192, aVh = stb + 16384, aVl = stb + 24576;
        const int kbase = kt * 64;

        // ---- S = Q K^T (3-pass split) ----
        float sacc[8][4];
        #pragma unroll
        for (int nb = 0; nb < 8; nb++)
            #pragma unroll
            for (int r = 0; r < 4; r++) sacc[nb][r] = 0.f;

        #pragma unroll
        for (int ks = 0; ks < 4; ks++) {
            const uint32_t coff = (uint32_t)((2 * ks + bkb) ^ bsw) * 16;
            uint32_t bfr[4][4];
            #pragma unroll
            for (int nt = 0; nt < 4; nt++)
                ldsm4(bfr[nt], aKh + (uint32_t)(nt * 16 + brow) * 128 + coff);
            #pragma unroll
            for (int nb = 0; nb < 8; nb++)
                mma16816(sacc[nb], qfh[ks], &bfr[nb >> 1][(nb & 1) * 2]);   // Qhi*Khi
            #pragma unroll
            for (int nb = 0; nb < 8; nb++)
                mma16816(sacc[nb], qfl[ks], &bfr[nb >> 1][(nb & 1) * 2]);   // Qlo*Khi
            #pragma unroll
            for (int nt = 0; nt < 4; nt++)
                ldsm4(bfr[nt], aKl + (uint32_t)(nt * 16 + brow) * 128 + coff);
            #pragma unroll
            for (int nb = 0; nb < 8; nb++)
                mma16816(sacc[nb], qfh[ks], &bfr[nb >> 1][(nb & 1) * 2]);   // Qhi*Klo
        }

        // ---- causal mask (tiles reaching past this warp's rows) ----
        if (kbase + 63 > q0 + wm) {
            #pragma unroll
            for (int nb = 0; nb < 8; nb++) {
                const int key = kbase + nb * 8 + tig;
                if (key     > r0) sacc[nb][0] = -1e30f;
                if (key + 1 > r0) sacc[nb][1] = -1e30f;
                if (key     > r1) sacc[nb][2] = -1e30f;
                if (key + 1 > r1) sacc[nb][3] = -1e30f;
            }
        }

        // ---- online softmax ----
        float mx0 = -1e30f, mx1 = -1e30f;
        #pragma unroll
        for (int nb = 0; nb < 8; nb++) {
            mx0 = fmaxf(mx0, fmaxf(sacc[nb][0], sacc[nb][1]));
            mx1 = fmaxf(mx1, fmaxf(sacc[nb][2], sacc[nb][3]));
        }
        mx0 = fmaxf(mx0, __shfl_xor_sync(0xffffffffu, mx0, 1));
        mx0 = fmaxf(mx0, __shfl_xor_sync(0xffffffffu, mx0, 2));
        mx1 = fmaxf(mx1, __shfl_xor_sync(0xffffffffu, mx1, 1));
        mx1 = fmaxf(mx1, __shfl_xor_sync(0xffffffffu, mx1, 2));
        const float mn0 = fmaxf(m0, mx0), mn1 = fmaxf(m1, mx1);
        const float cf0 = __expf(m0 - mn0), cf1 = __expf(m1 - mn1);
        m0 = mn0; m1 = mn1;
        l0 *= cf0; l1 *= cf1;
        #pragma unroll
        for (int nb = 0; nb < 8; nb++) {
            O[nb][0] *= cf0; O[nb][1] *= cf0;
            O[nb][2] *= cf1; O[nb][3] *= cf1;
        }
        float ps0 = 0.f, ps1 = 0.f;
        #pragma unroll
        for (int nb = 0; nb < 8; nb++) {
            const float p0 = __expf(sacc[nb][0] - m0);
            const float p1 = __expf(sacc[nb][1] - m0);
            const float p2 = __expf(sacc[nb][2] - m1);
            const float p3 = __expf(sacc[nb][3] - m1);
            sacc[nb][0] = p0; sacc[nb][1] = p1; sacc[nb][2] = p2; sacc[nb][3] = p3;
            ps0 += p0 + p1; ps1 += p2 + p3;
        }
        ps0 += __shfl_xor_sync(0xffffffffu, ps0, 1);
        ps0 += __shfl_xor_sync(0xffffffffu, ps0, 2);
        ps1 += __shfl_xor_sync(0xffffffffu, ps1, 1);
        ps1 += __shfl_xor_sync(0xffffffffu, ps1, 2);
        l0 += ps0; l1 += ps1;

        // ---- O += P V (3-pass split; P frags straight from registers) ----
        #pragma unroll
        for (int ks = 0; ks < 4; ks++) {
            uint32_t pah[4], pal[4];
            split2(sacc[2*ks  ][0], sacc[2*ks  ][1], pah[0], pal[0]);
            split2(sacc[2*ks  ][2], sacc[2*ks  ][3], pah[1], pal[1]);
            split2(sacc[2*ks+1][0], sacc[2*ks+1][1], pah[2], pal[2]);
            split2(sacc[2*ks+1][2], sacc[2*ks+1][3], pah[3], pal[3]);
            const uint32_t coff = (uint32_t)((2 * ks + bkb) ^ bsw) * 16;
            uint32_t bfr[4][4];
            #pragma unroll
            for (int nt = 0; nt < 4; nt++)
                ldsm4(bfr[nt], aVh + (uint32_t)(nt * 16 + brow) * 128 + coff);
            #pragma unroll
            for (int nb = 0; nb < 8; nb++)
                mma16816(O[nb], pah, &bfr[nb >> 1][(nb & 1) * 2]);   // Phi*Vhi
            #pragma unroll
            for (int nb = 0; nb < 8; nb++)
                mma16816(O[nb], pal, &bfr[nb >> 1][(nb & 1) * 2]);   // Plo*Vhi
            #pragma unroll
            for (int nt = 0; nt < 4; nt++)
                ldsm4(bfr[nt], aVl + (uint32_t)(nt * 16 + brow) * 128 + coff);
            #pragma unroll
            for (int nb = 0; nb < 8; nb++)
                mma16816(O[nb], pah, &bfr[nb >> 1][(nb & 1) * 2]);   // Phi*Vlo
        }
    }

    // ---- finalize: masked-part fixup, normalize, split to bf16 hi/lo, write ----
    const float em0 = __expf(-m0), em1 = __expf(-m1);
    const float lt0 = l0 + (float)(SS - 1 - r0) * em0;
    const float lt1 = l1 + (float)(SS - 1 - r1) * em1;
    const float inv0 = 1.f / lt0, inv1 = 1.f / lt1;
    const int b_ = bh >> 4, h = bh & 15;
    const float* sp0 = sfx + ((size_t)bh * SS + r0) * HD;
    const float* sp1 = sfx + ((size_t)bh * SS + r1) * HD;
    const size_t i0 = ((size_t)(b_ * SS + r0)) * DD + h * HD;
    const size_t i1 = ((size_t)(b_ * SS + r1)) * DD + h * HD;
    #pragma unroll
    for (int nb = 0; nb < 8; nb++) {
        const int d = nb * 8 + tig;
        const float2 sv0 = *(const float2*)(sp0 + d);
        const float2 sv1 = *(const float2*)(sp1 + d);
        const float w00 = (O[nb][0] + em0 * sv0.x) * inv0;
        const float w01 = (O[nb][1] + em0 * sv0.y) * inv0;
        const float w10 = (O[nb][2] + em1 * sv1.x) * inv1;
        const float w11 = (O[nb][3] + em1 * sv1.y) * inv1;
        uint32_t hh, ll;
        split2(w00, w01, hh, ll);
        *(uint32_t*)(cth + i0 + d) = hh;
        *(uint32_t*)(ctl + i0 + d) = ll;
        split2(w10, w11, hh, ll);
        *(uint32_t*)(cth + i1 + d) = hh;
        *(uint32_t*)(ctl + i1 + d) = ll;
    }
}

// ---------------- LayerNorm (in place on d_out) ----------------
__global__ __launch_bounds__(256)
void ln_k(float* __restrict__ out, const float* __restrict__ gamma,
          const float* __restrict__ beta)
{
    const int row = blockIdx.x;
    float* p = out + (size_t)row*DD;
    const int t = threadIdx.x;
    float4 v = ((const float4*)p)[t];
    float sum = v.x + v.y + v.z + v.w;
    float sq  = v.x*v.x + v.y*v.y + v.z*v.z + v.w*v.w;
    #pragma unroll
    for (int o = 16; o > 0; o >>= 1) {
        sum += __shfl_xor_sync(0xffffffffu, sum, o);
        sq  += __shfl_xor_sync(0xffffffffu, sq,  o);
    }
    __shared__ float s1[8], s2[8];
    if ((t & 31) == 0) { s1[t >> 5] = sum; s2[t >> 5] = sq; }
    __syncthreads();
    __shared__ float smu, srstd;
    if (t < 32) {
        float a = (t < 8) ? s1[t] : 0.f;
        float b = (t < 8) ? s2[t] : 0.f;
        #pragma unroll
        for (int o = 4; o > 0; o >>= 1) {
            a += __shfl_xor_sync(0xffffffffu, a, o);
            b += __shfl_xor_sync(0xffffffffu, b, o);
        }
        if (t == 0) {
            float mu  = a * (1.f/DD);
            float var = b * (1.f/DD) - mu*mu;
            smu = mu;
            srstd = rsqrtf(var + 1e-5f);
        }
    }
    __syncthreads();
    const float mu = smu, rs = srstd;
    float4 gm = ((const float4*)gamma)[t];
    float4 be = ((const float4*)beta)[t];
    v.x = (v.x - mu)*rs*gm.x + be.x;
    v.y = (v.y - mu)*rs*gm.y + be.y;
    v.z = (v.z - mu)*rs*gm.z + be.z;
    v.w = (v.w - mu)*rs*gm.w + be.w;
    ((float4*)p)[t] = v;
}

// ---------------- launch ----------------
extern "C" void kernel_launch(void* const* d_in, const int* in_sizes, int n_in,
                              void* d_out, int out_size)
{
    const float* q     = (const float*)d_in[0];
    const float* k     = (const float*)d_in[1];
    const float* v     = (const float*)d_in[2];
    const float* Wq    = (const float*)d_in[3];
    const float* bq    = (const float*)d_in[4];
    const float* Wk    = (const float*)d_in[5];
    const float* bk    = (const float*)d_in[6];
    const float* Wv    = (const float*)d_in[7];
    const float* bv    = (const float*)d_in[8];
    const float* Wp    = (const float*)d_in[9];
    const float* bp    = (const float*)d_in[10];
    const float* gamma = (const float*)d_in[11];
    const float* beta  = (const float*)d_in[12];
    float* out = (float*)d_out;

    float *vh, *sfx, *ctot, *csfx;
    __nv_bfloat16 *qhh, *qhl, *khh, *khl, *vth, *vtl, *wth, *wtl;
    __nv_bfloat16 *ahq, *alq, *ahk, *alk, *ahv, *alv, *cth, *ctl;
    cudaGetSymbolAddress((void**)&qhh, g_qhh);
    cudaGetSymbolAddress((void**)&qhl, g_qhl);
    cudaGetSymbolAddress((void**)&khh, g_khh);
    cudaGetSymbolAddress((void**)&khl, g_khl);
    cudaGetSymbolAddress((void**)&vh,  g_vh);
    cudaGetSymbolAddress((void**)&vth, g_vth);
    cudaGetSymbolAddress((void**)&vtl, g_vtl);
    cudaGetSymbolAddress((void**)&sfx, g_sfx);
    cudaGetSymbolAddress((void**)&ctot, g_ctot);
    cudaGetSymbolAddress((void**)&csfx, g_csfx);
    cudaGetSymbolAddress((void**)&wth, g_wth);
    cudaGetSymbolAddress((void**)&wtl, g_wtl);
    cudaGetSymbolAddress((void**)&ahq, g_ahq);
    cudaGetSymbolAddress((void**)&alq, g_alq);
    cudaGetSymbolAddress((void**)&ahk, g_ahk);
    cudaGetSymbolAddress((void**)&alk, g_alk);
    cudaGetSymbolAddress((void**)&ahv, g_ahv);
    cudaGetSymbolAddress((void**)&alv, g_alv);
    cudaGetSymbolAddress((void**)&cth, g_cth);
    cudaGetSymbolAddress((void**)&ctl, g_ctl);

    cudaFuncSetAttribute(reinterpret_cast<const void*>(gemm_qkv),
                         cudaFuncAttributeMaxDynamicSharedMemorySize, 65536);
    cudaFuncSetAttribute(reinterpret_cast<const void*>(gemm_proj),
                         cudaFuncAttributeMaxDynamicSharedMemorySize, 65536);
    cudaFuncSetAttribute(reinterpret_cast<const void*>(attn_mma),
                         cudaFuncAttributeMaxDynamicSharedMemorySize, 98304);

    // weights: transpose + hi/lo split (one launch, grid.z = 4)
    convW4_k<<<dim3(32, 32, 4), dim3(32, 32)>>>(Wq, Wk, Wv, Wp, wth, wtl);
    // activations: hi/lo split x3 (one launch, grid.z = 3)
    convA3_k<<<dim3(2048, 1, 3), 1024>>>(q, k, v, ahq, alq, ahk, alk, ahv, alv);

    // QKV projections (one launch, grid.z = 3)
    gemm_qkv<<<dim3(DD/128, MM/128, 3), 256, 65536>>>(
        ahq, alq, ahk, alk, ahv, alv, wth, wtl, bq, bk, bv,
        qhh, qhl, khh, khl, vh);

    dim3 gs(32, NBH);
    sfxA_k<<<gs, 64>>>(vh, sfx, ctot);
    sfxB_k<<<NBH, 64>>>(ctot, csfx);
    sfxC_k<<<gs, 64>>>(csfx, sfx);
    convVT_k<<<dim3(SS/32, HD/32, NBH), dim3(32, 32)>>>(vh, vth, vtl);

    attn_mma<<<dim3(SS/BQ, NBH), 256, 98304>>>(qhh, qhl, khh, khl, vth, vtl, sfx,
                                               cth, ctl);

    gemm_proj<<<dim3(DD/128, MM/128), 256, 65536>>>(
        cth, ctl, wth + 3*(size_t)WSZ, wtl + 3*(size_t)WSZ, bp, q, out);
    ln_k<<<MM, 256>>>(out, gamma, beta);
}